// round 1
// baseline (speedup 1.0000x reference)
#include <cuda_runtime.h>
#include <cuda_bf16.h>
#include <math.h>

#define DIM 128
#define MAXN 50000
#define MAXE 600000

// ---------------- device scratch (no allocations allowed) ----------------
__device__ float g_S[(size_t)MAXN * DIM];      // aggregated sums
__device__ float g_tmp[(size_t)MAXN * DIM];    // tile_h after stage 2
__device__ int   g_cnt[MAXN];
__device__ int   g_rowptr[MAXN + 1];
__device__ int   g_cursor[MAXN];
__device__ int   g_srclist[MAXE];
__device__ float g_WT[3 * 256 * DIM];          // combined transposed weights per stage
__device__ float g_bc[3 * DIM];                // combined bias per stage

// ---------------- weight prep: WT[s][k][j] = k<128 ? Wu[j][k] : (Wu2@Wm)[j][k-128]
__global__ void prep_weights_kernel(
    const float* __restrict__ W_t2p, const float* __restrict__ b_t2p, const float* __restrict__ W_pu,
    const float* __restrict__ W_p2t, const float* __restrict__ b_p2t, const float* __restrict__ W_tup,
    const float* __restrict__ W_t2t, const float* __restrict__ b_t2t, const float* __restrict__ W_tut)
{
    int s = blockIdx.y;
    int j = blockIdx.x;      // output column (0..127)
    int k = threadIdx.x;     // k index (0..127)

    const float *Wm, *Wu, *bm;
    if (s == 0)      { Wm = W_t2p; Wu = W_pu;  bm = b_t2p; }
    else if (s == 1) { Wm = W_p2t; Wu = W_tup; bm = b_p2t; }
    else             { Wm = W_t2t; Wu = W_tut; bm = b_t2t; }

    float* WTs = g_WT + (size_t)s * 256 * DIM;

    // first half: transpose of Wu1
    WTs[k * DIM + j] = Wu[j * 256 + k];

    // second half: Wc[j][k] = sum_l Wu[j][128+l] * Wm[l][k], stored transposed
    float acc = 0.f;
    #pragma unroll 8
    for (int l = 0; l < 128; l++)
        acc = fmaf(Wu[j * 256 + 128 + l], Wm[l * DIM + k], acc);
    WTs[(128 + k) * DIM + j] = acc;

    if (k == 0) {
        float a = 0.f;
        for (int l = 0; l < 128; l++)
            a = fmaf(Wu[j * 256 + 128 + l], bm[l], a);
        g_bc[s * DIM + j] = a;
    }
}

// ---------------- CSR build ----------------
__global__ void count_kernel(const int* __restrict__ dst, int E)
{
    int e = blockIdx.x * blockDim.x + threadIdx.x;
    if (e < E) atomicAdd(&g_cnt[dst[e]], 1);
}

__global__ void scan_kernel(int N)
{
    __shared__ int sums[1024];
    int t = threadIdx.x;
    int chunk = (N + 1023) >> 10;
    int lo = t * chunk;
    int hi = lo + chunk; if (hi > N) hi = N;
    if (lo > N) lo = N;

    int local = 0;
    for (int i = lo; i < hi; i++) local += g_cnt[i];
    sums[t] = local;
    __syncthreads();
    // Hillis-Steele inclusive scan
    for (int off = 1; off < 1024; off <<= 1) {
        int v = (t >= off) ? sums[t - off] : 0;
        __syncthreads();
        sums[t] += v;
        __syncthreads();
    }
    int run = sums[t] - local;   // exclusive prefix
    for (int i = lo; i < hi; i++) {
        g_rowptr[i] = run;
        g_cursor[i] = run;
        run += g_cnt[i];
    }
    if (hi == N) g_rowptr[N] = run;
}

__global__ void fill_kernel(const int* __restrict__ src, const int* __restrict__ dst, int E)
{
    int e = blockIdx.x * blockDim.x + threadIdx.x;
    if (e < E) {
        int d = dst[e];
        int pos = atomicAdd(&g_cursor[d], 1);
        g_srclist[pos] = src[e];
    }
}

// ---------------- aggregation: warp per destination row ----------------
__global__ void agg_kernel(const float* __restrict__ H, int N)
{
    int w = (blockIdx.x * blockDim.x + threadIdx.x) >> 5;
    int lane = threadIdx.x & 31;
    if (w >= N) return;
    int s0 = g_rowptr[w];
    int s1 = g_rowptr[w + 1];
    float4 acc = make_float4(0.f, 0.f, 0.f, 0.f);
    for (int i = s0; i < s1; i++) {
        int s = g_srclist[i];
        const float4 v = *(const float4*)(H + (size_t)s * DIM + lane * 4);
        acc.x += v.x; acc.y += v.y; acc.z += v.z; acc.w += v.w;
    }
    *(float4*)(g_S + (size_t)w * DIM + lane * 4) = acc;
}

// ---------------- fused update GEMM ----------------
// out[i,:] = relu( [h_i , inv_i*S_i] @ WT + m_i*bc + bu )
// 64 rows x 128 cols per block, K=256 in chunks of 32, 8x4 micro-tile.
__global__ __launch_bounds__(256) void update_kernel(
    const float* __restrict__ H, const float* __restrict__ WT,
    const float* __restrict__ bc, const float* __restrict__ bu,
    float* __restrict__ out, int N)
{
    __shared__ __align__(16) float Xs[64][36];   // 32 k-values + pad
    __shared__ __align__(16) float Ws[32][128];
    __shared__ float invs[64];
    __shared__ float ms[64];

    int t  = threadIdx.x;
    int r0 = blockIdx.x * 64;
    int tr = t >> 5;     // 0..7
    int tc = t & 31;     // 0..31

    if (t < 64) {
        int row = r0 + t;
        int c = (row < N) ? g_cnt[row] : 0;
        invs[t] = (c > 0) ? (1.f / (float)c) : 1.f;
        ms[t]   = (c > 0) ? 1.f : 0.f;
    }

    float acc[8][4];
    #pragma unroll
    for (int i = 0; i < 8; i++)
        #pragma unroll
        for (int c = 0; c < 4; c++) acc[i][c] = 0.f;

    for (int kc = 0; kc < 8; kc++) {
        __syncthreads();
        // load X tile: 64 rows x 32 k
        #pragma unroll
        for (int q = 0; q < 2; q++) {
            int id = t + 256 * q;        // 0..511 float4 slots
            int rl = id >> 3;            // row 0..63
            int c4 = id & 7;             // float4 within row
            int kg = kc * 32 + c4 * 4;   // global k
            int row = r0 + rl;
            float4 v = make_float4(0.f, 0.f, 0.f, 0.f);
            if (row < N) {
                if (kg < 128) {
                    v = *(const float4*)(H + (size_t)row * DIM + kg);
                } else {
                    v = *(const float4*)(g_S + (size_t)row * DIM + (kg - 128));
                    float iv = invs[rl];
                    v.x *= iv; v.y *= iv; v.z *= iv; v.w *= iv;
                }
            }
            *(float4*)&Xs[rl][c4 * 4] = v;
        }
        // load W tile: 32 k x 128 cols
        #pragma unroll
        for (int q = 0; q < 4; q++) {
            int id = t + 256 * q;        // 0..1023 float4 slots
            int kl = id >> 5;            // 0..31
            int j4 = id & 31;
            *(float4*)&Ws[kl][j4 * 4] =
                *(const float4*)(WT + (size_t)(kc * 32 + kl) * DIM + j4 * 4);
        }
        __syncthreads();

        #pragma unroll 4
        for (int kl = 0; kl < 32; kl++) {
            float4 b = *(float4*)&Ws[kl][tc * 4];
            #pragma unroll
            for (int i = 0; i < 8; i++) {
                float a = Xs[tr * 8 + i][kl];
                acc[i][0] = fmaf(a, b.x, acc[i][0]);
                acc[i][1] = fmaf(a, b.y, acc[i][1]);
                acc[i][2] = fmaf(a, b.z, acc[i][2]);
                acc[i][3] = fmaf(a, b.w, acc[i][3]);
            }
        }
    }

    float4 bu4 = *(const float4*)(bu + tc * 4);
    float4 bc4 = *(const float4*)(bc + tc * 4);
    #pragma unroll
    for (int i = 0; i < 8; i++) {
        int row = r0 + tr * 8 + i;
        if (row < N) {
            float mm = ms[tr * 8 + i];
            float4 o;
            o.x = fmaxf(acc[i][0] + bu4.x + mm * bc4.x, 0.f);
            o.y = fmaxf(acc[i][1] + bu4.y + mm * bc4.y, 0.f);
            o.z = fmaxf(acc[i][2] + bu4.z + mm * bc4.z, 0.f);
            o.w = fmaxf(acc[i][3] + bu4.w + mm * bc4.w, 0.f);
            *(float4*)(out + (size_t)row * DIM + tc * 4) = o;
        }
    }
}

// ---------------- host orchestration ----------------
static void run_stage(const float* H_gather, const int* src, const int* dst, int E,
                      int N_dst, const float* H_self,
                      const float* WT_s, const float* bc_s, const float* bu_s,
                      float* out, int* cnt_p)
{
    cudaMemsetAsync(cnt_p, 0, (size_t)N_dst * sizeof(int));
    count_kernel<<<(E + 255) / 256, 256>>>(dst, E);
    scan_kernel<<<1, 1024>>>(N_dst);
    fill_kernel<<<(E + 255) / 256, 256>>>(src, dst, E);
    agg_kernel<<<(N_dst + 7) / 8, 256>>>(H_gather, N_dst);
    update_kernel<<<(N_dst + 63) / 64, 256>>>(H_self, WT_s, bc_s, bu_s, out, N_dst);
}

extern "C" void kernel_launch(void* const* d_in, const int* in_sizes, int n_in,
                              void* d_out, int out_size)
{
    const float* tile_h    = (const float*)d_in[0];
    const float* piece_h   = (const float*)d_in[1];
    const int*   tile_src  = (const int*)d_in[2];
    const int*   piece_dst = (const int*)d_in[3];
    const int*   piece_src = (const int*)d_in[4];
    const int*   tile_dst  = (const int*)d_in[5];
    const int*   t_src     = (const int*)d_in[6];
    const int*   t_dst     = (const int*)d_in[7];
    const float* W_t2p = (const float*)d_in[8];
    const float* b_t2p = (const float*)d_in[9];
    // W_pu = d_in[10], b_pu = d_in[11]
    const float* W_p2t = (const float*)d_in[12];
    const float* b_p2t = (const float*)d_in[13];
    // W_tup = d_in[14], b_tup = d_in[15]
    const float* W_t2t = (const float*)d_in[16];
    const float* b_t2t = (const float*)d_in[17];
    // W_tut = d_in[18], b_tut = d_in[19]

    int NT  = in_sizes[0] / DIM;
    int NP  = in_sizes[1] / DIM;
    int EPT = in_sizes[2];
    int ETT = in_sizes[6];

    float* out       = (float*)d_out;
    float* out_tile  = out;
    float* out_piece = out + (size_t)NT * DIM;

    // resolve device scratch addresses
    float *S_p, *tmp_p, *WT_p, *bc_p;
    int *cnt_p;
    cudaGetSymbolAddress((void**)&S_p, g_S);
    cudaGetSymbolAddress((void**)&tmp_p, g_tmp);
    cudaGetSymbolAddress((void**)&WT_p, g_WT);
    cudaGetSymbolAddress((void**)&bc_p, g_bc);
    cudaGetSymbolAddress((void**)&cnt_p, g_cnt);

    prep_weights_kernel<<<dim3(128, 3), 128>>>(
        W_t2p, b_t2p, (const float*)d_in[10],
        W_p2t, b_p2t, (const float*)d_in[14],
        W_t2t, b_t2t, (const float*)d_in[18]);

    // Stage 1: tile -> piece (writes final piece output)
    run_stage(tile_h, tile_src, piece_dst, EPT, NP, piece_h,
              WT_p + 0 * 256 * DIM, bc_p + 0 * DIM, (const float*)d_in[11],
              out_piece, cnt_p);

    // Stage 2: piece -> tile (uses updated piece_h)
    run_stage(out_piece, piece_src, tile_dst, EPT, NT, tile_h,
              WT_p + 1 * 256 * DIM, bc_p + 1 * DIM, (const float*)d_in[15],
              tmp_p, cnt_p);

    // Stage 3: tile -> tile (writes final tile output)
    run_stage(tmp_p, t_src, t_dst, ETT, NT, tmp_p,
              WT_p + 2 * 256 * DIM, bc_p + 2 * DIM, (const float*)d_in[19],
              out_tile, cnt_p);
}

// round 2
// speedup vs baseline: 1.0523x; 1.0523x over previous
#include <cuda_runtime.h>
#include <cuda_bf16.h>
#include <math.h>

#define DIM 128
#define MAXN 50000
#define MAXE 600000
typedef unsigned long long ull;

// ---------------- device scratch ----------------
__device__ float g_S[(size_t)MAXN * DIM];        // aggregated sums (reused per stage)
__device__ float g_tmp[(size_t)MAXN * DIM];      // tile_h after stage 2
__device__ int   g_cnt[3][MAXN];
__device__ int   g_rowptr[3][MAXN + 1];
__device__ int   g_cursor[3][MAXN];
__device__ int   g_srclist[3][MAXE];
__device__ float g_WT[3 * 256 * DIM];            // combined transposed weights
__device__ float g_bc[3 * DIM];                  // combined bias

__device__ __forceinline__ ull ffma2(ull a, ull b, ull c) {
    ull d;
    asm("fma.rn.f32x2 %0, %1, %2, %3;" : "=l"(d) : "l"(a), "l"(b), "l"(c));
    return d;
}

// ---------------- weight prep ----------------
__global__ void prep_weights_kernel(
    const float* __restrict__ W_t2p, const float* __restrict__ b_t2p, const float* __restrict__ W_pu,
    const float* __restrict__ W_p2t, const float* __restrict__ b_p2t, const float* __restrict__ W_tup,
    const float* __restrict__ W_t2t, const float* __restrict__ b_t2t, const float* __restrict__ W_tut)
{
    int s = blockIdx.y;
    int j = blockIdx.x;
    int k = threadIdx.x;

    const float *Wm, *Wu, *bm;
    if (s == 0)      { Wm = W_t2p; Wu = W_pu;  bm = b_t2p; }
    else if (s == 1) { Wm = W_p2t; Wu = W_tup; bm = b_p2t; }
    else             { Wm = W_t2t; Wu = W_tut; bm = b_t2t; }

    float* WTs = g_WT + (size_t)s * 256 * DIM;
    WTs[k * DIM + j] = Wu[j * 256 + k];

    float acc = 0.f;
    #pragma unroll 8
    for (int l = 0; l < 128; l++)
        acc = fmaf(Wu[j * 256 + 128 + l], Wm[l * DIM + k], acc);
    WTs[(128 + k) * DIM + j] = acc;

    if (k == 0) {
        float a = 0.f;
        for (int l = 0; l < 128; l++)
            a = fmaf(Wu[j * 256 + 128 + l], bm[l], a);
        g_bc[s * DIM + j] = a;
    }
}

// ---------------- batched CSR build (all 3 stages in one launch each) ----------------
__global__ void count3_kernel(const int* __restrict__ d0, int E0,
                              const int* __restrict__ d1, int E1,
                              const int* __restrict__ d2, int E2)
{
    int s = blockIdx.y;
    const int* dst = (s == 0) ? d0 : (s == 1) ? d1 : d2;
    int E = (s == 0) ? E0 : (s == 1) ? E1 : E2;
    int e = blockIdx.x * blockDim.x + threadIdx.x;
    if (e < E) atomicAdd(&g_cnt[s][dst[e]], 1);
}

__global__ void scan3_kernel(int N0, int N1, int N2)
{
    __shared__ int sums[1024];
    int s = blockIdx.x;
    int N = (s == 0) ? N0 : (s == 1) ? N1 : N2;
    int* cnt = g_cnt[s];
    int* rowptr = g_rowptr[s];
    int* cursor = g_cursor[s];

    int t = threadIdx.x;
    int chunk = (N + 1023) >> 10;
    int lo = t * chunk;
    int hi = lo + chunk; if (hi > N) hi = N;
    if (lo > N) lo = N;

    int local = 0;
    for (int i = lo; i < hi; i++) local += cnt[i];
    sums[t] = local;
    __syncthreads();
    for (int off = 1; off < 1024; off <<= 1) {
        int v = (t >= off) ? sums[t - off] : 0;
        __syncthreads();
        sums[t] += v;
        __syncthreads();
    }
    int run = sums[t] - local;
    for (int i = lo; i < hi; i++) {
        rowptr[i] = run;
        cursor[i] = run;
        run += cnt[i];
    }
    if (hi == N) rowptr[N] = run;
}

__global__ void fill3_kernel(const int* __restrict__ s0, const int* __restrict__ d0, int E0,
                             const int* __restrict__ s1, const int* __restrict__ d1, int E1,
                             const int* __restrict__ s2, const int* __restrict__ d2, int E2)
{
    int s = blockIdx.y;
    const int* src = (s == 0) ? s0 : (s == 1) ? s1 : s2;
    const int* dst = (s == 0) ? d0 : (s == 1) ? d1 : d2;
    int E = (s == 0) ? E0 : (s == 1) ? E1 : E2;
    int e = blockIdx.x * blockDim.x + threadIdx.x;
    if (e < E) {
        int d = dst[e];
        int pos = atomicAdd(&g_cursor[s][d], 1);
        g_srclist[s][pos] = src[e];
    }
}

// ---------------- aggregation: warp per destination row ----------------
__global__ void agg_kernel(int stage, const float* __restrict__ H, int N)
{
    int w = (blockIdx.x * blockDim.x + threadIdx.x) >> 5;
    int lane = threadIdx.x & 31;
    if (w >= N) return;
    const int* rowptr = g_rowptr[stage];
    const int* srclist = g_srclist[stage];
    int s0 = rowptr[w];
    int s1 = rowptr[w + 1];
    float4 acc = make_float4(0.f, 0.f, 0.f, 0.f);
    for (int i = s0; i < s1; i++) {
        int s = srclist[i];
        const float4 v = *(const float4*)(H + (size_t)s * DIM + lane * 4);
        acc.x += v.x; acc.y += v.y; acc.z += v.z; acc.w += v.w;
    }
    *(float4*)(g_S + (size_t)w * DIM + lane * 4) = acc;
}

// ---------------- fused update GEMM with packed f32x2 FMA ----------------
// 128 rows x 128 cols per block, 256 threads, 8x8 micro-tile.
// Xs staged duplicated as float2{v,v} so A operand is a direct LDS.64.
#define SMEM_UPD (128*32*8 + 32*128*4 + 128*4 + 128*4)

__global__ __launch_bounds__(256) void update_kernel(
    int stage, const float* __restrict__ H, const float* __restrict__ WT,
    const float* __restrict__ bc, const float* __restrict__ bu,
    float* __restrict__ out, int N)
{
    extern __shared__ __align__(16) char smem[];
    float2 (*Xs2)[32] = (float2(*)[32])smem;                     // 32768 B
    float  (*Ws)[128] = (float(*)[128])(smem + 32768);           // 16384 B
    float* invs = (float*)(smem + 32768 + 16384);                // 512 B
    float* ms   = invs + 128;                                    // 512 B

    int t  = threadIdx.x;
    int r0 = blockIdx.x * 128;
    int tr = t >> 4;      // 0..15 -> rows tr*8..tr*8+7
    int tc = t & 15;      // 0..15 -> cols tc*8..tc*8+7

    if (t < 128) {
        int row = r0 + t;
        int c = (row < N) ? g_cnt[stage][row] : 0;
        invs[t] = (c > 0) ? (1.f / (float)c) : 1.f;
        ms[t]   = (c > 0) ? 1.f : 0.f;
    }

    ull acc[8][4];
    #pragma unroll
    for (int i = 0; i < 8; i++)
        #pragma unroll
        for (int p = 0; p < 4; p++) acc[i][p] = 0ull;

    for (int kc = 0; kc < 8; kc++) {
        __syncthreads();
        // X tile: 128 rows x 32 k, duplicated pairs. 1024 float4 source slots.
        #pragma unroll
        for (int q = 0; q < 4; q++) {
            int id = t + 256 * q;
            int rl = id >> 3;             // row 0..127
            int c4 = id & 7;              // float4 slot within 32-k chunk
            int kg = kc * 32 + c4 * 4;
            int row = r0 + rl;
            float4 v = make_float4(0.f, 0.f, 0.f, 0.f);
            if (row < N) {
                if (kg < 128) {
                    v = *(const float4*)(H + (size_t)row * DIM + kg);
                } else {
                    v = *(const float4*)(g_S + (size_t)row * DIM + (kg - 128));
                    float iv = invs[rl];
                    v.x *= iv; v.y *= iv; v.z *= iv; v.w *= iv;
                }
            }
            float4* dst = (float4*)&Xs2[rl][c4 * 4];
            dst[0] = make_float4(v.x, v.x, v.y, v.y);
            dst[1] = make_float4(v.z, v.z, v.w, v.w);
        }
        // W tile: 32 k x 128 cols
        #pragma unroll
        for (int q = 0; q < 4; q++) {
            int id = t + 256 * q;
            int kl = id >> 5;
            int j4 = id & 31;
            *(float4*)&Ws[kl][j4 * 4] =
                *(const float4*)(WT + (size_t)(kc * 32 + kl) * DIM + j4 * 4);
        }
        __syncthreads();

        #pragma unroll 8
        for (int kl = 0; kl < 32; kl++) {
            const ull* bp = (const ull*)&Ws[kl][tc * 8];   // 4 packed b-pairs
            ull b0 = bp[0], b1 = bp[1], b2 = bp[2], b3 = bp[3];
            #pragma unroll
            for (int i = 0; i < 8; i++) {
                ull a = *(const ull*)&Xs2[tr * 8 + i][kl];
                acc[i][0] = ffma2(a, b0, acc[i][0]);
                acc[i][1] = ffma2(a, b1, acc[i][1]);
                acc[i][2] = ffma2(a, b2, acc[i][2]);
                acc[i][3] = ffma2(a, b3, acc[i][3]);
            }
        }
    }

    float4 buA = *(const float4*)(bu + tc * 8);
    float4 buB = *(const float4*)(bu + tc * 8 + 4);
    float4 bcA = *(const float4*)(bc + tc * 8);
    float4 bcB = *(const float4*)(bc + tc * 8 + 4);

    #pragma unroll
    for (int i = 0; i < 8; i++) {
        int row = r0 + tr * 8 + i;
        if (row < N) {
            float mm = ms[tr * 8 + i];
            float2 p0 = *(float2*)&acc[i][0];
            float2 p1 = *(float2*)&acc[i][1];
            float2 p2 = *(float2*)&acc[i][2];
            float2 p3 = *(float2*)&acc[i][3];
            float4 oA, oB;
            oA.x = fmaxf(p0.x + buA.x + mm * bcA.x, 0.f);
            oA.y = fmaxf(p0.y + buA.y + mm * bcA.y, 0.f);
            oA.z = fmaxf(p1.x + buA.z + mm * bcA.z, 0.f);
            oA.w = fmaxf(p1.y + buA.w + mm * bcA.w, 0.f);
            oB.x = fmaxf(p2.x + buB.x + mm * bcB.x, 0.f);
            oB.y = fmaxf(p2.y + buB.y + mm * bcB.y, 0.f);
            oB.z = fmaxf(p3.x + buB.z + mm * bcB.z, 0.f);
            oB.w = fmaxf(p3.y + buB.w + mm * bcB.w, 0.f);
            *(float4*)(out + (size_t)row * DIM + tc * 8)     = oA;
            *(float4*)(out + (size_t)row * DIM + tc * 8 + 4) = oB;
        }
    }
}

// ---------------- host orchestration ----------------
extern "C" void kernel_launch(void* const* d_in, const int* in_sizes, int n_in,
                              void* d_out, int out_size)
{
    const float* tile_h    = (const float*)d_in[0];
    const float* piece_h   = (const float*)d_in[1];
    const int*   tile_src  = (const int*)d_in[2];
    const int*   piece_dst = (const int*)d_in[3];
    const int*   piece_src = (const int*)d_in[4];
    const int*   tile_dst  = (const int*)d_in[5];
    const int*   t_src     = (const int*)d_in[6];
    const int*   t_dst     = (const int*)d_in[7];

    int NT  = in_sizes[0] / DIM;
    int NP  = in_sizes[1] / DIM;
    int EPT = in_sizes[2];
    int ETT = in_sizes[6];

    float* out       = (float*)d_out;
    float* out_tile  = out;
    float* out_piece = out + (size_t)NT * DIM;

    float *tmp_p, *WT_p, *bc_p;
    int *cnt_p;
    cudaGetSymbolAddress((void**)&tmp_p, g_tmp);
    cudaGetSymbolAddress((void**)&WT_p, g_WT);
    cudaGetSymbolAddress((void**)&bc_p, g_bc);
    cudaGetSymbolAddress((void**)&cnt_p, g_cnt);

    cudaFuncSetAttribute(update_kernel,
                         cudaFuncAttributeMaxDynamicSharedMemorySize, SMEM_UPD);

    prep_weights_kernel<<<dim3(128, 3), 128>>>(
        (const float*)d_in[8],  (const float*)d_in[9],  (const float*)d_in[10],
        (const float*)d_in[12], (const float*)d_in[13], (const float*)d_in[14],
        (const float*)d_in[16], (const float*)d_in[17], (const float*)d_in[18]);

    // CSR build for all three stages (edge lists are pure inputs)
    cudaMemsetAsync(cnt_p, 0, 3 * (size_t)MAXN * sizeof(int));
    int maxE = ETT > EPT ? ETT : EPT;
    dim3 cg((maxE + 255) / 256, 3);
    count3_kernel<<<cg, 256>>>(piece_dst, EPT, tile_dst, EPT, t_dst, ETT);
    scan3_kernel<<<3, 1024>>>(NP, NT, NT);
    fill3_kernel<<<cg, 256>>>(tile_src, piece_dst, EPT,
                              piece_src, tile_dst, EPT,
                              t_src, t_dst, ETT);

    // Stage 1: tile -> piece
    agg_kernel<<<(NP + 7) / 8, 256>>>(0, tile_h, NP);
    update_kernel<<<(NP + 127) / 128, 256, SMEM_UPD>>>(
        0, piece_h, WT_p + 0 * 256 * DIM, bc_p + 0 * DIM,
        (const float*)d_in[11], out_piece, NP);

    // Stage 2: piece -> tile
    agg_kernel<<<(NT + 7) / 8, 256>>>(1, out_piece, NT);
    update_kernel<<<(NT + 127) / 128, 256, SMEM_UPD>>>(
        1, tile_h, WT_p + 1 * 256 * DIM, bc_p + 1 * DIM,
        (const float*)d_in[15], tmp_p, NT);

    // Stage 3: tile -> tile
    agg_kernel<<<(NT + 7) / 8, 256>>>(2, tmp_p, NT);
    update_kernel<<<(NT + 127) / 128, 256, SMEM_UPD>>>(
        2, tmp_p, WT_p + 2 * 256 * DIM, bc_p + 2 * DIM,
        (const float*)d_in[19], out_tile, NT);
}

// round 4
// speedup vs baseline: 1.7930x; 1.7039x over previous
#include <cuda_runtime.h>
#include <cuda_bf16.h>
#include <cstdint>
#include <math.h>

#define DIM 128
#define MAXN 50000
#define MAXE 600000

// ---------------- device scratch ----------------
__device__ float g_S[(size_t)MAXN * DIM];        // aggregated sums
__device__ float g_tmp[(size_t)MAXN * DIM];      // tile_h after stage 2
__device__ int   g_cnt[3][MAXN];
__device__ int   g_rowptr[3][MAXN + 1];
__device__ int   g_cursor[3][MAXN];
__device__ int   g_srclist[3][MAXE];
__device__ float g_W2[3 * 128 * 256];            // combined weights [s][n][k], tf32-rounded
__device__ float g_bc[3 * DIM];                  // combined bias (fp32)

__device__ __forceinline__ float to_tf32(float x) {
    float r;
    asm("cvt.rna.tf32.f32 %0, %1;" : "=f"(r) : "f"(x));
    return r;
}

__device__ __forceinline__ void mma_tf32(float* c, const uint32_t* a, uint32_t b0, uint32_t b1) {
    asm volatile(
        "mma.sync.aligned.m16n8k8.row.col.f32.tf32.tf32.f32 "
        "{%0,%1,%2,%3}, {%4,%5,%6,%7}, {%8,%9}, {%0,%1,%2,%3};"
        : "+f"(c[0]), "+f"(c[1]), "+f"(c[2]), "+f"(c[3])
        : "r"(a[0]), "r"(a[1]), "r"(a[2]), "r"(a[3]), "r"(b0), "r"(b1));
}

// ---------------- weight prep ----------------
__global__ void prep_weights_kernel(
    const float* __restrict__ W_t2p, const float* __restrict__ b_t2p, const float* __restrict__ W_pu,
    const float* __restrict__ W_p2t, const float* __restrict__ b_p2t, const float* __restrict__ W_tup,
    const float* __restrict__ W_t2t, const float* __restrict__ b_t2t, const float* __restrict__ W_tut)
{
    int s = blockIdx.y;
    int j = blockIdx.x;      // output column n (0..127)
    int k = threadIdx.x;     // k (0..127)

    const float *Wm, *Wu, *bm;
    if (s == 0)      { Wm = W_t2p; Wu = W_pu;  bm = b_t2p; }
    else if (s == 1) { Wm = W_p2t; Wu = W_tup; bm = b_p2t; }
    else             { Wm = W_t2t; Wu = W_tut; bm = b_t2t; }

    float* W2s = g_W2 + (size_t)s * 128 * 256;
    W2s[j * 256 + k] = to_tf32(Wu[j * 256 + k]);

    float acc = 0.f;
    #pragma unroll 8
    for (int l = 0; l < 128; l++)
        acc = fmaf(Wu[j * 256 + 128 + l], Wm[l * DIM + k], acc);
    W2s[j * 256 + 128 + k] = to_tf32(acc);

    if (k == 0) {
        float a = 0.f;
        for (int l = 0; l < 128; l++)
            a = fmaf(Wu[j * 256 + 128 + l], bm[l], a);
        g_bc[s * DIM + j] = a;
    }
}

// ---------------- batched CSR build ----------------
__global__ void count3_kernel(const int* __restrict__ d0, int E0,
                              const int* __restrict__ d1, int E1,
                              const int* __restrict__ d2, int E2)
{
    int s = blockIdx.y;
    const int* dst = (s == 0) ? d0 : (s == 1) ? d1 : d2;
    int E = (s == 0) ? E0 : (s == 1) ? E1 : E2;
    int e = blockIdx.x * blockDim.x + threadIdx.x;
    if (e < E) atomicAdd(&g_cnt[s][dst[e]], 1);
}

__global__ void scan3_kernel(int N0, int N1, int N2)
{
    __shared__ int sums[1024];
    int s = blockIdx.x;
    int N = (s == 0) ? N0 : (s == 1) ? N1 : N2;
    int* cnt = g_cnt[s];
    int* rowptr = g_rowptr[s];
    int* cursor = g_cursor[s];

    int t = threadIdx.x;
    int chunk = (N + 1023) >> 10;
    int lo = t * chunk;
    int hi = lo + chunk; if (hi > N) hi = N;
    if (lo > N) lo = N;

    int local = 0;
    for (int i = lo; i < hi; i++) local += cnt[i];
    sums[t] = local;
    __syncthreads();
    for (int off = 1; off < 1024; off <<= 1) {
        int v = (t >= off) ? sums[t - off] : 0;
        __syncthreads();
        sums[t] += v;
        __syncthreads();
    }
    int run = sums[t] - local;
    for (int i = lo; i < hi; i++) {
        rowptr[i] = run;
        cursor[i] = run;
        run += cnt[i];
    }
    if (hi == N) rowptr[N] = run;
}

__global__ void fill3_kernel(const int* __restrict__ s0, const int* __restrict__ d0, int E0,
                             const int* __restrict__ s1, const int* __restrict__ d1, int E1,
                             const int* __restrict__ s2, const int* __restrict__ d2, int E2)
{
    int s = blockIdx.y;
    const int* src = (s == 0) ? s0 : (s == 1) ? s1 : s2;
    const int* dst = (s == 0) ? d0 : (s == 1) ? d1 : d2;
    int E = (s == 0) ? E0 : (s == 1) ? E1 : E2;
    int e = blockIdx.x * blockDim.x + threadIdx.x;
    if (e < E) {
        int d = dst[e];
        int pos = atomicAdd(&g_cursor[s][d], 1);
        g_srclist[s][pos] = src[e];
    }
}

// ---------------- aggregation: warp per destination row ----------------
__global__ void agg_kernel(int stage, const float* __restrict__ H, int N)
{
    int w = (blockIdx.x * blockDim.x + threadIdx.x) >> 5;
    int lane = threadIdx.x & 31;
    if (w >= N) return;
    const int* rowptr = g_rowptr[stage];
    const int* srclist = g_srclist[stage];
    int s0 = rowptr[w];
    int s1 = rowptr[w + 1];
    float4 acc = make_float4(0.f, 0.f, 0.f, 0.f);
    for (int i = s0; i < s1; i++) {
        int s = srclist[i];
        const float4 v = *(const float4*)(H + (size_t)s * DIM + lane * 4);
        acc.x += v.x; acc.y += v.y; acc.z += v.z; acc.w += v.w;
    }
    *(float4*)(g_S + (size_t)w * DIM + lane * 4) = acc;
}

// ---------------- tf32 mma.sync update GEMM ----------------
// CTA: 128 rows x 128 cols, K=256 in 8 chunks of 32.
// 8 warps: warp_m = wid>>1 (32 rows each), warp_n = wid&1 (64 cols each).
// Per warp: 2 m-tiles (m16) x 8 n-tiles (n8), k-steps of 8.
#define XSTR 36   // padded smem row stride (floats): bank = (4g + t4) conflict-free

__global__ __launch_bounds__(256) void update_mma_kernel(
    int stage, const float* __restrict__ H, const float* __restrict__ W2,
    const float* __restrict__ bc, const float* __restrict__ bu,
    float* __restrict__ out, int N)
{
    __shared__ uint32_t As[128 * XSTR];
    __shared__ uint32_t Bs[128 * XSTR];
    __shared__ float invs[128], ms[128], bus[128], bcs[128];

    int t = threadIdx.x;
    int r0 = blockIdx.x * 128;

    if (t < 128) {
        int row = r0 + t;
        int c = (row < N) ? g_cnt[stage][row] : 0;
        invs[t] = (c > 0) ? (1.f / (float)c) : 1.f;
        ms[t]   = (c > 0) ? 1.f : 0.f;
        bus[t]  = bu[t];
        bcs[t]  = bc[t];
    }
    __syncthreads();

    int lane = t & 31;
    int wid  = t >> 5;
    int g  = lane >> 2;      // group id 0..7
    int t4 = lane & 3;       // thread-in-group 0..3
    int wm = wid >> 1;       // 0..3
    int wn = wid & 1;        // 0..1

    float acc[2][8][4];
    #pragma unroll
    for (int mt = 0; mt < 2; mt++)
        #pragma unroll
        for (int nt = 0; nt < 8; nt++)
            #pragma unroll
            for (int i = 0; i < 4; i++) acc[mt][nt][i] = 0.f;

    for (int kc = 0; kc < 8; kc++) {
        __syncthreads();
        // stage A chunk: 128 rows x 32 k (1024 float4 slots, 4 per thread)
        #pragma unroll
        for (int q = 0; q < 4; q++) {
            int id = t + 256 * q;
            int rl = id >> 3;            // row 0..127
            int c4 = id & 7;             // float4 slot
            int kg = kc * 32 + c4 * 4;
            int row = r0 + rl;
            float4 v = make_float4(0.f, 0.f, 0.f, 0.f);
            if (row < N) {
                if (kg < 128) {
                    v = *(const float4*)(H + (size_t)row * DIM + kg);
                } else {
                    v = *(const float4*)(g_S + (size_t)row * DIM + (kg - 128));
                    float iv = invs[rl];
                    v.x *= iv; v.y *= iv; v.z *= iv; v.w *= iv;
                }
            }
            v.x = to_tf32(v.x); v.y = to_tf32(v.y); v.z = to_tf32(v.z); v.w = to_tf32(v.w);
            uint32_t* d = &As[rl * XSTR + c4 * 4];
            d[0] = __float_as_uint(v.x); d[1] = __float_as_uint(v.y);
            d[2] = __float_as_uint(v.z); d[3] = __float_as_uint(v.w);
        }
        // stage B chunk: 128 n x 32 k (weights already tf32-rounded)
        #pragma unroll
        for (int q = 0; q < 4; q++) {
            int id = t + 256 * q;
            int nl = id >> 3;
            int c4 = id & 7;
            float4 v = *(const float4*)(W2 + (size_t)nl * 256 + kc * 32 + c4 * 4);
            uint32_t* d = &Bs[nl * XSTR + c4 * 4];
            d[0] = __float_as_uint(v.x); d[1] = __float_as_uint(v.y);
            d[2] = __float_as_uint(v.z); d[3] = __float_as_uint(v.w);
        }
        __syncthreads();

        #pragma unroll
        for (int kk = 0; kk < 4; kk++) {
            int kb = kk * 8 + t4;
            uint32_t a[2][4];
            #pragma unroll
            for (int mt = 0; mt < 2; mt++) {
                int rbase = (wm * 32 + mt * 16 + g) * XSTR + kb;
                a[mt][0] = As[rbase];
                a[mt][1] = As[rbase + 8 * XSTR];
                a[mt][2] = As[rbase + 4];
                a[mt][3] = As[rbase + 8 * XSTR + 4];
            }
            #pragma unroll
            for (int nt = 0; nt < 8; nt++) {
                int bbase = (wn * 64 + nt * 8 + g) * XSTR + kb;
                uint32_t b0 = Bs[bbase];
                uint32_t b1 = Bs[bbase + 4];
                mma_tf32(acc[0][nt], a[0], b0, b1);
                mma_tf32(acc[1][nt], a[1], b0, b1);
            }
        }
    }

    // epilogue: bias + masked combined-bias + relu
    #pragma unroll
    for (int mt = 0; mt < 2; mt++) {
        int row1 = r0 + wm * 32 + mt * 16 + g;
        int row2 = row1 + 8;
        int rl1 = wm * 32 + mt * 16 + g;
        float m1 = ms[rl1], m2 = ms[rl1 + 8];
        #pragma unroll
        for (int nt = 0; nt < 8; nt++) {
            int col = wn * 64 + nt * 8 + t4 * 2;
            float bu0 = bus[col], bu1 = bus[col + 1];
            float bc0 = bcs[col], bc1 = bcs[col + 1];
            if (row1 < N) {
                float2 o;
                o.x = fmaxf(acc[mt][nt][0] + bu0 + m1 * bc0, 0.f);
                o.y = fmaxf(acc[mt][nt][1] + bu1 + m1 * bc1, 0.f);
                *(float2*)(out + (size_t)row1 * DIM + col) = o;
            }
            if (row2 < N) {
                float2 o;
                o.x = fmaxf(acc[mt][nt][2] + bu0 + m2 * bc0, 0.f);
                o.y = fmaxf(acc[mt][nt][3] + bu1 + m2 * bc1, 0.f);
                *(float2*)(out + (size_t)row2 * DIM + col) = o;
            }
        }
    }
}

// ---------------- host orchestration ----------------
extern "C" void kernel_launch(void* const* d_in, const int* in_sizes, int n_in,
                              void* d_out, int out_size)
{
    const float* tile_h    = (const float*)d_in[0];
    const float* piece_h   = (const float*)d_in[1];
    const int*   tile_src  = (const int*)d_in[2];
    const int*   piece_dst = (const int*)d_in[3];
    const int*   piece_src = (const int*)d_in[4];
    const int*   tile_dst  = (const int*)d_in[5];
    const int*   t_src     = (const int*)d_in[6];
    const int*   t_dst     = (const int*)d_in[7];

    int NT  = in_sizes[0] / DIM;
    int NP  = in_sizes[1] / DIM;
    int EPT = in_sizes[2];
    int ETT = in_sizes[6];

    float* out       = (float*)d_out;
    float* out_tile  = out;
    float* out_piece = out + (size_t)NT * DIM;

    float *tmp_p, *W2_p, *bc_p;
    int *cnt_p;
    cudaGetSymbolAddress((void**)&tmp_p, g_tmp);
    cudaGetSymbolAddress((void**)&W2_p, g_W2);
    cudaGetSymbolAddress((void**)&bc_p, g_bc);
    cudaGetSymbolAddress((void**)&cnt_p, g_cnt);

    prep_weights_kernel<<<dim3(128, 3), 128>>>(
        (const float*)d_in[8],  (const float*)d_in[9],  (const float*)d_in[10],
        (const float*)d_in[12], (const float*)d_in[13], (const float*)d_in[14],
        (const float*)d_in[16], (const float*)d_in[17], (const float*)d_in[18]);

    cudaMemsetAsync(cnt_p, 0, 3 * (size_t)MAXN * sizeof(int));
    int maxE = ETT > EPT ? ETT : EPT;
    dim3 cg((maxE + 255) / 256, 3);
    count3_kernel<<<cg, 256>>>(piece_dst, EPT, tile_dst, EPT, t_dst, ETT);
    scan3_kernel<<<3, 1024>>>(NP, NT, NT);
    fill3_kernel<<<cg, 256>>>(tile_src, piece_dst, EPT,
                              piece_src, tile_dst, EPT,
                              t_src, t_dst, ETT);

    // Stage 1: tile -> piece
    agg_kernel<<<(NP + 7) / 8, 256>>>(0, tile_h, NP);
    update_mma_kernel<<<(NP + 127) / 128, 256>>>(
        0, piece_h, W2_p + 0 * 128 * 256, bc_p + 0 * DIM,
        (const float*)d_in[11], out_piece, NP);

    // Stage 2: piece -> tile
    agg_kernel<<<(NT + 7) / 8, 256>>>(1, out_piece, NT);
    update_mma_kernel<<<(NT + 127) / 128, 256>>>(
        1, tile_h, W2_p + 1 * 128 * 256, bc_p + 1 * DIM,
        (const float*)d_in[15], tmp_p, NT);

    // Stage 3: tile -> tile
    agg_kernel<<<(NT + 7) / 8, 256>>>(2, tmp_p, NT);
    update_mma_kernel<<<(NT + 127) / 128, 256>>>(
        2, tmp_p, W2_p + 2 * 128 * 256, bc_p + 2 * DIM,
        (const float*)d_in[19], out_tile, NT);
}

// round 5
// speedup vs baseline: 2.3930x; 1.3346x over previous
#include <cuda_runtime.h>
#include <cuda_fp16.h>
#include <cstdint>
#include <math.h>

#define DIM 128
#define MAXN 50000
#define MAXP 25000
#define MAXE 600000

// ---------------- device scratch ----------------
__device__ __half g_th16[(size_t)MAXN * DIM];    // tile_h input, fp16
__device__ __half g_ph16[(size_t)MAXP * DIM];    // piece_h input, fp16
__device__ __half g_pout16[(size_t)MAXP * DIM];  // stage-1 piece output, fp16
__device__ __half g_tout16[(size_t)MAXN * DIM];  // stage-2 tile output, fp16
__device__ __half g_S16[(size_t)MAXN * DIM];     // aggregated means, fp16
__device__ __half g_W216[3 * 128 * 256];         // combined weights [s][n][k], fp16
__device__ float  g_bc[3 * DIM];                 // combined bias (fp32)
__device__ int    g_cnt[3][MAXN];
__device__ int    g_rowptr[3][MAXN + 1];
__device__ int    g_cursor[3][MAXN];
__device__ int    g_srclist[3][MAXE];

__device__ __forceinline__ void mma_f16(float* c, const uint32_t* a, uint32_t b0, uint32_t b1) {
    asm volatile(
        "mma.sync.aligned.m16n8k16.row.col.f32.f16.f16.f32 "
        "{%0,%1,%2,%3}, {%4,%5,%6,%7}, {%8,%9}, {%0,%1,%2,%3};"
        : "+f"(c[0]), "+f"(c[1]), "+f"(c[2]), "+f"(c[3])
        : "r"(a[0]), "r"(a[1]), "r"(a[2]), "r"(a[3]), "r"(b0), "r"(b1));
}

// ---------------- input conversion: fp32 -> fp16 ----------------
__global__ void convert_kernel(const float* __restrict__ th, int nt,
                               const float* __restrict__ ph, int np)
{
    int i = blockIdx.x * blockDim.x + threadIdx.x;
    int tot = nt + np;
    if (i >= tot) return;
    if (i < nt) {
        float4 v = *(const float4*)(th + (size_t)i * 4);
        __half2* d = (__half2*)(g_th16 + (size_t)i * 4);
        d[0] = __floats2half2_rn(v.x, v.y);
        d[1] = __floats2half2_rn(v.z, v.w);
    } else {
        int j = i - nt;
        float4 v = *(const float4*)(ph + (size_t)j * 4);
        __half2* d = (__half2*)(g_ph16 + (size_t)j * 4);
        d[0] = __floats2half2_rn(v.x, v.y);
        d[1] = __floats2half2_rn(v.z, v.w);
    }
}

// ---------------- weight prep (combined weights, fp16) ----------------
__global__ void prep_weights_kernel(
    const float* __restrict__ W_t2p, const float* __restrict__ b_t2p, const float* __restrict__ W_pu,
    const float* __restrict__ W_p2t, const float* __restrict__ b_p2t, const float* __restrict__ W_tup,
    const float* __restrict__ W_t2t, const float* __restrict__ b_t2t, const float* __restrict__ W_tut)
{
    int s = blockIdx.y;
    int j = blockIdx.x;      // output column n (0..127)
    int k = threadIdx.x;     // k (0..127)

    const float *Wm, *Wu, *bm;
    if (s == 0)      { Wm = W_t2p; Wu = W_pu;  bm = b_t2p; }
    else if (s == 1) { Wm = W_p2t; Wu = W_tup; bm = b_p2t; }
    else             { Wm = W_t2t; Wu = W_tut; bm = b_t2t; }

    __half* W2s = g_W216 + (size_t)s * 128 * 256;
    W2s[j * 256 + k] = __float2half_rn(Wu[j * 256 + k]);

    float acc = 0.f;
    #pragma unroll 8
    for (int l = 0; l < 128; l++)
        acc = fmaf(Wu[j * 256 + 128 + l], Wm[l * DIM + k], acc);
    W2s[j * 256 + 128 + k] = __float2half_rn(acc);

    if (k == 0) {
        float a = 0.f;
        for (int l = 0; l < 128; l++)
            a = fmaf(Wu[j * 256 + 128 + l], bm[l], a);
        g_bc[s * DIM + j] = a;
    }
}

// ---------------- batched CSR build ----------------
__global__ void count3_kernel(const int* __restrict__ d0, int E0,
                              const int* __restrict__ d1, int E1,
                              const int* __restrict__ d2, int E2)
{
    int s = blockIdx.y;
    const int* dst = (s == 0) ? d0 : (s == 1) ? d1 : d2;
    int E = (s == 0) ? E0 : (s == 1) ? E1 : E2;
    int e = blockIdx.x * blockDim.x + threadIdx.x;
    if (e < E) atomicAdd(&g_cnt[s][dst[e]], 1);
}

__global__ void scan3_kernel(int N0, int N1, int N2)
{
    __shared__ int sums[1024];
    int s = blockIdx.x;
    int N = (s == 0) ? N0 : (s == 1) ? N1 : N2;
    int* cnt = g_cnt[s];
    int* rowptr = g_rowptr[s];
    int* cursor = g_cursor[s];

    int t = threadIdx.x;
    int chunk = (N + 1023) >> 10;
    int lo = t * chunk;
    int hi = lo + chunk; if (hi > N) hi = N;
    if (lo > N) lo = N;

    int local = 0;
    for (int i = lo; i < hi; i++) local += cnt[i];
    sums[t] = local;
    __syncthreads();
    for (int off = 1; off < 1024; off <<= 1) {
        int v = (t >= off) ? sums[t - off] : 0;
        __syncthreads();
        sums[t] += v;
        __syncthreads();
    }
    int run = sums[t] - local;
    for (int i = lo; i < hi; i++) {
        rowptr[i] = run;
        cursor[i] = run;
        run += cnt[i];
    }
    if (hi == N) rowptr[N] = run;
}

__global__ void fill3_kernel(const int* __restrict__ s0, const int* __restrict__ d0, int E0,
                             const int* __restrict__ s1, const int* __restrict__ d1, int E1,
                             const int* __restrict__ s2, const int* __restrict__ d2, int E2)
{
    int s = blockIdx.y;
    const int* src = (s == 0) ? s0 : (s == 1) ? s1 : s2;
    const int* dst = (s == 0) ? d0 : (s == 1) ? d1 : d2;
    int E = (s == 0) ? E0 : (s == 1) ? E1 : E2;
    int e = blockIdx.x * blockDim.x + threadIdx.x;
    if (e < E) {
        int d = dst[e];
        int pos = atomicAdd(&g_cursor[s][d], 1);
        g_srclist[s][pos] = src[e];
    }
}

// ---------------- aggregation: warp per destination row, fp16 in/out ----------------
// Writes MEAN (scaled by 1/cnt) directly.
__global__ void agg_kernel(int stage, const __half* __restrict__ H, int N)
{
    int w = (blockIdx.x * blockDim.x + threadIdx.x) >> 5;
    int lane = threadIdx.x & 31;
    if (w >= N) return;
    const int* rowptr = g_rowptr[stage];
    const int* srclist = g_srclist[stage];
    int s0 = rowptr[w];
    int s1 = rowptr[w + 1];
    float acc0 = 0.f, acc1 = 0.f, acc2 = 0.f, acc3 = 0.f;
    for (int i = s0; i < s1; i++) {
        int s = srclist[i];
        uint2 v = *(const uint2*)(H + (size_t)s * DIM + lane * 4);
        float2 f0 = __half22float2(*(__half2*)&v.x);
        float2 f1 = __half22float2(*(__half2*)&v.y);
        acc0 += f0.x; acc1 += f0.y; acc2 += f1.x; acc3 += f1.y;
    }
    int cn = s1 - s0;
    float inv = (cn > 0) ? (1.f / (float)cn) : 0.f;
    uint2 o;
    *(__half2*)&o.x = __floats2half2_rn(acc0 * inv, acc1 * inv);
    *(__half2*)&o.y = __floats2half2_rn(acc2 * inv, acc3 * inv);
    *(uint2*)(g_S16 + (size_t)w * DIM + lane * 4) = o;
}

// ---------------- fp16 mma.sync update GEMM ----------------
// CTA: 128 rows x 128 cols, K=256 in 4 chunks of 64.
// 8 warps: wm = wid>>1 (32 rows), wn = wid&1 (64 cols). m16n8k16 tiles.
#define XSTRH 72   // smem row stride in halves: bank = (4g + t4) conflict-free

__global__ __launch_bounds__(256) void update_mma_kernel(
    int stage, const __half* __restrict__ H,
    const float* __restrict__ bu,
    float* __restrict__ out32, __half* __restrict__ out16, int N)
{
    __shared__ __half As[128 * XSTRH];
    __shared__ __half Bs[128 * XSTRH];
    __shared__ float ms[128], bus[128], bcs[128];

    int t = threadIdx.x;
    int r0 = blockIdx.x * 128;
    const __half* W2 = g_W216 + (size_t)stage * 128 * 256;

    if (t < 128) {
        int row = r0 + t;
        int c = (row < N) ? g_cnt[stage][row] : 0;
        ms[t]  = (c > 0) ? 1.f : 0.f;
        bus[t] = bu[t];
        bcs[t] = g_bc[stage * DIM + t];
    }

    int lane = t & 31;
    int wid  = t >> 5;
    int g  = lane >> 2;
    int t4 = lane & 3;
    int wm = wid >> 1;
    int wn = wid & 1;

    float acc[2][8][4];
    #pragma unroll
    for (int mt = 0; mt < 2; mt++)
        #pragma unroll
        for (int nt = 0; nt < 8; nt++)
            #pragma unroll
            for (int i = 0; i < 4; i++) acc[mt][nt][i] = 0.f;

    for (int kc = 0; kc < 4; kc++) {
        __syncthreads();
        // stage A chunk: 128 rows x 64 halves (1024 uint4 slots, 4/thread)
        #pragma unroll
        for (int q = 0; q < 4; q++) {
            int id = t + 256 * q;
            int rl = id >> 3;            // row 0..127
            int c8 = id & 7;             // uint4 slot (8 halves)
            int kg = kc * 64 + c8 * 8;
            int row = r0 + rl;
            uint4 v = make_uint4(0u, 0u, 0u, 0u);
            if (row < N) {
                const __half* src = (kg < 128)
                    ? (H + (size_t)row * DIM + kg)
                    : (g_S16 + (size_t)row * DIM + (kg - 128));
                v = *(const uint4*)src;
            }
            *(uint4*)&As[rl * XSTRH + c8 * 8] = v;
        }
        // stage B chunk: 128 n x 64 halves
        #pragma unroll
        for (int q = 0; q < 4; q++) {
            int id = t + 256 * q;
            int nl = id >> 3;
            int c8 = id & 7;
            uint4 v = *(const uint4*)(W2 + (size_t)nl * 256 + kc * 64 + c8 * 8);
            *(uint4*)&Bs[nl * XSTRH + c8 * 8] = v;
        }
        __syncthreads();

        #pragma unroll
        for (int ks = 0; ks < 4; ks++) {
            int kb = ks * 16;
            uint32_t a[2][4];
            #pragma unroll
            for (int mt = 0; mt < 2; mt++) {
                int rbase = (wm * 32 + mt * 16 + g) * XSTRH + kb + t4 * 2;
                a[mt][0] = *(const uint32_t*)&As[rbase];
                a[mt][1] = *(const uint32_t*)&As[rbase + 8 * XSTRH];
                a[mt][2] = *(const uint32_t*)&As[rbase + 8];
                a[mt][3] = *(const uint32_t*)&As[rbase + 8 * XSTRH + 8];
            }
            #pragma unroll
            for (int nt = 0; nt < 8; nt++) {
                int bbase = (wn * 64 + nt * 8 + g) * XSTRH + kb + t4 * 2;
                uint32_t b0 = *(const uint32_t*)&Bs[bbase];
                uint32_t b1 = *(const uint32_t*)&Bs[bbase + 8];
                mma_f16(acc[0][nt], a[0], b0, b1);
                mma_f16(acc[1][nt], a[1], b0, b1);
            }
        }
    }

    // epilogue: bias + masked combined-bias + relu; fp32 and/or fp16 outputs
    #pragma unroll
    for (int mt = 0; mt < 2; mt++) {
        int rl1 = wm * 32 + mt * 16 + g;
        int row1 = r0 + rl1;
        int row2 = row1 + 8;
        float m1 = ms[rl1], m2 = ms[rl1 + 8];
        #pragma unroll
        for (int nt = 0; nt < 8; nt++) {
            int col = wn * 64 + nt * 8 + t4 * 2;
            float bu0 = bus[col], bu1 = bus[col + 1];
            float bc0 = bcs[col], bc1 = bcs[col + 1];
            float2 o1, o2;
            o1.x = fmaxf(acc[mt][nt][0] + bu0 + m1 * bc0, 0.f);
            o1.y = fmaxf(acc[mt][nt][1] + bu1 + m1 * bc1, 0.f);
            o2.x = fmaxf(acc[mt][nt][2] + bu0 + m2 * bc0, 0.f);
            o2.y = fmaxf(acc[mt][nt][3] + bu1 + m2 * bc1, 0.f);
            if (row1 < N) {
                if (out32) *(float2*)(out32 + (size_t)row1 * DIM + col) = o1;
                if (out16) *(__half2*)(out16 + (size_t)row1 * DIM + col) = __floats2half2_rn(o1.x, o1.y);
            }
            if (row2 < N) {
                if (out32) *(float2*)(out32 + (size_t)row2 * DIM + col) = o2;
                if (out16) *(__half2*)(out16 + (size_t)row2 * DIM + col) = __floats2half2_rn(o2.x, o2.y);
            }
        }
    }
}

// ---------------- host orchestration ----------------
extern "C" void kernel_launch(void* const* d_in, const int* in_sizes, int n_in,
                              void* d_out, int out_size)
{
    const float* tile_h    = (const float*)d_in[0];
    const float* piece_h   = (const float*)d_in[1];
    const int*   tile_src  = (const int*)d_in[2];
    const int*   piece_dst = (const int*)d_in[3];
    const int*   piece_src = (const int*)d_in[4];
    const int*   tile_dst  = (const int*)d_in[5];
    const int*   t_src     = (const int*)d_in[6];
    const int*   t_dst     = (const int*)d_in[7];

    int NT  = in_sizes[0] / DIM;
    int NP  = in_sizes[1] / DIM;
    int EPT = in_sizes[2];
    int ETT = in_sizes[6];

    float* out       = (float*)d_out;
    float* out_tile  = out;
    float* out_piece = out + (size_t)NT * DIM;

    __half *th16_p, *ph16_p, *pout16_p, *tout16_p;
    int *cnt_p;
    cudaGetSymbolAddress((void**)&th16_p, g_th16);
    cudaGetSymbolAddress((void**)&ph16_p, g_ph16);
    cudaGetSymbolAddress((void**)&pout16_p, g_pout16);
    cudaGetSymbolAddress((void**)&tout16_p, g_tout16);
    cudaGetSymbolAddress((void**)&cnt_p, g_cnt);

    // convert inputs to fp16 (vector of 4 floats per thread)
    int convN = NT * 32 + NP * 32;  // (N*128)/4 slots
    convert_kernel<<<(convN + 255) / 256, 256>>>(tile_h, NT * 32, piece_h, NP * 32);

    prep_weights_kernel<<<dim3(128, 3), 128>>>(
        (const float*)d_in[8],  (const float*)d_in[9],  (const float*)d_in[10],
        (const float*)d_in[12], (const float*)d_in[13], (const float*)d_in[14],
        (const float*)d_in[16], (const float*)d_in[17], (const float*)d_in[18]);

    cudaMemsetAsync(cnt_p, 0, 3 * (size_t)MAXN * sizeof(int));
    int maxE = ETT > EPT ? ETT : EPT;
    dim3 cg((maxE + 255) / 256, 3);
    count3_kernel<<<cg, 256>>>(piece_dst, EPT, tile_dst, EPT, t_dst, ETT);
    scan3_kernel<<<3, 1024>>>(NP, NT, NT);
    fill3_kernel<<<cg, 256>>>(tile_src, piece_dst, EPT,
                              piece_src, tile_dst, EPT,
                              t_src, t_dst, ETT);

    // Stage 1: tile -> piece (fp32 final piece output + fp16 for stage-2 gather)
    agg_kernel<<<(NP + 7) / 8, 256>>>(0, th16_p, NP);
    update_mma_kernel<<<(NP + 127) / 128, 256>>>(
        0, ph16_p, (const float*)d_in[11], out_piece, pout16_p, NP);

    // Stage 2: piece -> tile (fp16 only; feeds stage 3)
    agg_kernel<<<(NT + 7) / 8, 256>>>(1, pout16_p, NT);
    update_mma_kernel<<<(NT + 127) / 128, 256>>>(
        1, th16_p, (const float*)d_in[15], nullptr, tout16_p, NT);

    // Stage 3: tile -> tile (fp32 final tile output)
    agg_kernel<<<(NT + 7) / 8, 256>>>(2, tout16_p, NT);
    update_mma_kernel<<<(NT + 127) / 128, 256>>>(
        2, tout16_p, (const float*)d_in[19], out_tile, nullptr, NT);
}

// round 6
// speedup vs baseline: 3.2620x; 1.3632x over previous
#include <cuda_runtime.h>
#include <cuda_fp16.h>
#include <cstdint>
#include <math.h>

#define DIM 128
#define MAXN 50000
#define MAXP 25000
#define MAXE 600000
#define TILE 4096
#define MAXTILES 16

// ---------------- device scratch ----------------
__device__ __half g_th16[(size_t)MAXN * DIM];    // tile_h input, fp16
__device__ __half g_ph16[(size_t)MAXP * DIM];    // piece_h input, fp16
__device__ __half g_pout16[(size_t)MAXP * DIM];  // stage-1 piece output, fp16
__device__ __half g_tout16[(size_t)MAXN * DIM];  // stage-2 tile output, fp16
__device__ __half g_S16[(size_t)MAXN * DIM];     // aggregated means, fp16
__device__ __half g_W216[3 * 128 * 256];         // combined weights [s][n][k], fp16
__device__ float  g_bc[3 * DIM];                 // combined bias (fp32)
__device__ int    g_cnt[3][MAXN];
__device__ int    g_rowptr[3][MAXN + 1];
__device__ int    g_cursor[3][MAXN];
__device__ int    g_srclist[3][MAXE];
__device__ int    g_tilesum[3][MAXTILES];
__device__ int    g_tileoff[3][MAXTILES];

__device__ __forceinline__ void mma_f16(float* c, const uint32_t* a, uint32_t b0, uint32_t b1) {
    asm volatile(
        "mma.sync.aligned.m16n8k16.row.col.f32.f16.f16.f32 "
        "{%0,%1,%2,%3}, {%4,%5,%6,%7}, {%8,%9}, {%0,%1,%2,%3};"
        : "+f"(c[0]), "+f"(c[1]), "+f"(c[2]), "+f"(c[3])
        : "r"(a[0]), "r"(a[1]), "r"(a[2]), "r"(a[3]), "r"(b0), "r"(b1));
}

// ---------------- input conversion: fp32 -> fp16 ----------------
__global__ void convert_kernel(const float* __restrict__ th, int nt,
                               const float* __restrict__ ph, int np)
{
    int i = blockIdx.x * blockDim.x + threadIdx.x;
    int tot = nt + np;
    if (i >= tot) return;
    if (i < nt) {
        float4 v = *(const float4*)(th + (size_t)i * 4);
        __half2* d = (__half2*)(g_th16 + (size_t)i * 4);
        d[0] = __floats2half2_rn(v.x, v.y);
        d[1] = __floats2half2_rn(v.z, v.w);
    } else {
        int j = i - nt;
        float4 v = *(const float4*)(ph + (size_t)j * 4);
        __half2* d = (__half2*)(g_ph16 + (size_t)j * 4);
        d[0] = __floats2half2_rn(v.x, v.y);
        d[1] = __floats2half2_rn(v.z, v.w);
    }
}

// ---------------- weight prep (combined weights, fp16) ----------------
__global__ void prep_weights_kernel(
    const float* __restrict__ W_t2p, const float* __restrict__ b_t2p, const float* __restrict__ W_pu,
    const float* __restrict__ W_p2t, const float* __restrict__ b_p2t, const float* __restrict__ W_tup,
    const float* __restrict__ W_t2t, const float* __restrict__ b_t2t, const float* __restrict__ W_tut)
{
    int s = blockIdx.y;
    int j = blockIdx.x;
    int k = threadIdx.x;

    const float *Wm, *Wu, *bm;
    if (s == 0)      { Wm = W_t2p; Wu = W_pu;  bm = b_t2p; }
    else if (s == 1) { Wm = W_p2t; Wu = W_tup; bm = b_p2t; }
    else             { Wm = W_t2t; Wu = W_tut; bm = b_t2t; }

    __half* W2s = g_W216 + (size_t)s * 128 * 256;
    W2s[j * 256 + k] = __float2half_rn(Wu[j * 256 + k]);

    float acc = 0.f;
    #pragma unroll 8
    for (int l = 0; l < 128; l++)
        acc = fmaf(Wu[j * 256 + 128 + l], Wm[l * DIM + k], acc);
    W2s[j * 256 + 128 + k] = __float2half_rn(acc);

    if (k == 0) {
        float a = 0.f;
        for (int l = 0; l < 128; l++)
            a = fmaf(Wu[j * 256 + 128 + l], bm[l], a);
        g_bc[s * DIM + j] = a;
    }
}

// ---------------- batched CSR build ----------------
__global__ void count3_kernel(const int* __restrict__ d0, int E0,
                              const int* __restrict__ d1, int E1,
                              const int* __restrict__ d2, int E2)
{
    int s = blockIdx.y;
    const int* dst = (s == 0) ? d0 : (s == 1) ? d1 : d2;
    int E = (s == 0) ? E0 : (s == 1) ? E1 : E2;
    int e = blockIdx.x * blockDim.x + threadIdx.x;
    if (e < E) atomicAdd(&g_cnt[s][dst[e]], 1);
}

// ---- scan phase A: per-tile sums (256 threads, 4096 ints/tile, int4 loads)
__global__ void tilesum_kernel(int N0, int N1, int N2)
{
    __shared__ int wsum[8];
    int s = blockIdx.y;
    int N = (s == 0) ? N0 : (s == 1) ? N1 : N2;
    int base = blockIdx.x * TILE;
    if (base >= N) return;
    const int* cnt = g_cnt[s];
    int t = threadIdx.x;
    int local = 0;
    #pragma unroll
    for (int q = 0; q < 4; q++) {
        int i = base + (t + q * 256) * 4;
        if (i + 3 < N) {
            int4 v = *(const int4*)(cnt + i);
            local += v.x + v.y + v.z + v.w;
        } else {
            for (int j = 0; j < 4; j++)
                if (i + j < N) local += cnt[i + j];
        }
    }
    // warp reduce
    #pragma unroll
    for (int off = 16; off > 0; off >>= 1)
        local += __shfl_down_sync(0xFFFFFFFF, local, off);
    if ((t & 31) == 0) wsum[t >> 5] = local;
    __syncthreads();
    if (t == 0) {
        int tot = 0;
        #pragma unroll
        for (int w = 0; w < 8; w++) tot += wsum[w];
        g_tilesum[s][blockIdx.x] = tot;
    }
}

// ---- scan phase B: tiny serial scan of tile sums (3 threads), writes rowptr[N]
__global__ void tileoff_kernel(int N0, int N1, int N2)
{
    int t = threadIdx.x;
    if (t >= 3) return;
    int N = (t == 0) ? N0 : (t == 1) ? N1 : N2;
    int ntiles = (N + TILE - 1) / TILE;
    int off = 0;
    for (int i = 0; i < ntiles; i++) {
        g_tileoff[t][i] = off;
        off += g_tilesum[t][i];
    }
    g_rowptr[t][N] = off;
}

// ---- scan phase C: per-tile block scan, coalesced rowptr/cursor writes
__global__ void scanC_kernel(int N0, int N1, int N2)
{
    __shared__ int wsum[8];
    __shared__ int wexcl[8];
    int s = blockIdx.y;
    int N = (s == 0) ? N0 : (s == 1) ? N1 : N2;
    int base = blockIdx.x * TILE;
    if (base >= N) return;
    const int* cnt = g_cnt[s];
    int* rowptr = g_rowptr[s];
    int* cursor = g_cursor[s];
    int t = threadIdx.x;
    int lane = t & 31, wid = t >> 5;
    int e0 = base + t * 16;

    int c[16];
    #pragma unroll
    for (int q = 0; q < 16; q++) {
        int i = e0 + q;
        c[q] = (i < N) ? cnt[i] : 0;
    }
    int tot = 0;
    #pragma unroll
    for (int q = 0; q < 16; q++) tot += c[q];

    // warp inclusive scan of per-thread totals
    int x = tot;
    #pragma unroll
    for (int off = 1; off < 32; off <<= 1) {
        int y = __shfl_up_sync(0xFFFFFFFF, x, off);
        if (lane >= off) x += y;
    }
    int texcl = x - tot;
    if (lane == 31) wsum[wid] = x;
    __syncthreads();
    if (t == 0) {
        int run = 0;
        #pragma unroll
        for (int w = 0; w < 8; w++) { wexcl[w] = run; run += wsum[w]; }
    }
    __syncthreads();

    int pre = g_tileoff[s][blockIdx.x] + wexcl[wid] + texcl;
    #pragma unroll
    for (int q = 0; q < 16; q++) {
        int i = e0 + q;
        if (i < N) { rowptr[i] = pre; cursor[i] = pre; }
        pre += c[q];
    }
}

__global__ void fill3_kernel(const int* __restrict__ s0, const int* __restrict__ d0, int E0,
                             const int* __restrict__ s1, const int* __restrict__ d1, int E1,
                             const int* __restrict__ s2, const int* __restrict__ d2, int E2)
{
    int s = blockIdx.y;
    const int* src = (s == 0) ? s0 : (s == 1) ? s1 : s2;
    const int* dst = (s == 0) ? d0 : (s == 1) ? d1 : d2;
    int E = (s == 0) ? E0 : (s == 1) ? E1 : E2;
    int e = blockIdx.x * blockDim.x + threadIdx.x;
    if (e < E) {
        int d = dst[e];
        int pos = atomicAdd(&g_cursor[s][d], 1);
        g_srclist[s][pos] = src[e];
    }
}

// ---------------- aggregation: warp per destination row, fp16 in/out ----------------
__global__ void agg_kernel(int stage, const __half* __restrict__ H, int N)
{
    int w = (blockIdx.x * blockDim.x + threadIdx.x) >> 5;
    int lane = threadIdx.x & 31;
    if (w >= N) return;
    const int* rowptr = g_rowptr[stage];
    const int* srclist = g_srclist[stage];
    int s0 = rowptr[w];
    int s1 = rowptr[w + 1];
    float acc0 = 0.f, acc1 = 0.f, acc2 = 0.f, acc3 = 0.f;
    for (int i = s0; i < s1; i++) {
        int s = srclist[i];
        uint2 v = *(const uint2*)(H + (size_t)s * DIM + lane * 4);
        float2 f0 = __half22float2(*(__half2*)&v.x);
        float2 f1 = __half22float2(*(__half2*)&v.y);
        acc0 += f0.x; acc1 += f0.y; acc2 += f1.x; acc3 += f1.y;
    }
    int cn = s1 - s0;
    float inv = (cn > 0) ? (1.f / (float)cn) : 0.f;
    uint2 o;
    *(__half2*)&o.x = __floats2half2_rn(acc0 * inv, acc1 * inv);
    *(__half2*)&o.y = __floats2half2_rn(acc2 * inv, acc3 * inv);
    *(uint2*)(g_S16 + (size_t)w * DIM + lane * 4) = o;
}

// ---------------- fp16 mma.sync update GEMM ----------------
#define XSTRH 72

__global__ __launch_bounds__(256) void update_mma_kernel(
    int stage, const __half* __restrict__ H,
    const float* __restrict__ bu,
    float* __restrict__ out32, __half* __restrict__ out16, int N)
{
    __shared__ __half As[128 * XSTRH];
    __shared__ __half Bs[128 * XSTRH];
    __shared__ float ms[128], bus[128], bcs[128];

    int t = threadIdx.x;
    int r0 = blockIdx.x * 128;
    const __half* W2 = g_W216 + (size_t)stage * 128 * 256;

    if (t < 128) {
        int row = r0 + t;
        int c = (row < N) ? g_cnt[stage][row] : 0;
        ms[t]  = (c > 0) ? 1.f : 0.f;
        bus[t] = bu[t];
        bcs[t] = g_bc[stage * DIM + t];
    }

    int lane = t & 31;
    int wid  = t >> 5;
    int g  = lane >> 2;
    int t4 = lane & 3;
    int wm = wid >> 1;
    int wn = wid & 1;

    float acc[2][8][4];
    #pragma unroll
    for (int mt = 0; mt < 2; mt++)
        #pragma unroll
        for (int nt = 0; nt < 8; nt++)
            #pragma unroll
            for (int i = 0; i < 4; i++) acc[mt][nt][i] = 0.f;

    for (int kc = 0; kc < 4; kc++) {
        __syncthreads();
        #pragma unroll
        for (int q = 0; q < 4; q++) {
            int id = t + 256 * q;
            int rl = id >> 3;
            int c8 = id & 7;
            int kg = kc * 64 + c8 * 8;
            int row = r0 + rl;
            uint4 v = make_uint4(0u, 0u, 0u, 0u);
            if (row < N) {
                const __half* src = (kg < 128)
                    ? (H + (size_t)row * DIM + kg)
                    : (g_S16 + (size_t)row * DIM + (kg - 128));
                v = *(const uint4*)src;
            }
            *(uint4*)&As[rl * XSTRH + c8 * 8] = v;
        }
        #pragma unroll
        for (int q = 0; q < 4; q++) {
            int id = t + 256 * q;
            int nl = id >> 3;
            int c8 = id & 7;
            uint4 v = *(const uint4*)(W2 + (size_t)nl * 256 + kc * 64 + c8 * 8);
            *(uint4*)&Bs[nl * XSTRH + c8 * 8] = v;
        }
        __syncthreads();

        #pragma unroll
        for (int ks = 0; ks < 4; ks++) {
            int kb = ks * 16;
            uint32_t a[2][4];
            #pragma unroll
            for (int mt = 0; mt < 2; mt++) {
                int rbase = (wm * 32 + mt * 16 + g) * XSTRH + kb + t4 * 2;
                a[mt][0] = *(const uint32_t*)&As[rbase];
                a[mt][1] = *(const uint32_t*)&As[rbase + 8 * XSTRH];
                a[mt][2] = *(const uint32_t*)&As[rbase + 8];
                a[mt][3] = *(const uint32_t*)&As[rbase + 8 * XSTRH + 8];
            }
            #pragma unroll
            for (int nt = 0; nt < 8; nt++) {
                int bbase = (wn * 64 + nt * 8 + g) * XSTRH + kb + t4 * 2;
                uint32_t b0 = *(const uint32_t*)&Bs[bbase];
                uint32_t b1 = *(const uint32_t*)&Bs[bbase + 8];
                mma_f16(acc[0][nt], a[0], b0, b1);
                mma_f16(acc[1][nt], a[1], b0, b1);
            }
        }
    }

    #pragma unroll
    for (int mt = 0; mt < 2; mt++) {
        int rl1 = wm * 32 + mt * 16 + g;
        int row1 = r0 + rl1;
        int row2 = row1 + 8;
        float m1 = ms[rl1], m2 = ms[rl1 + 8];
        #pragma unroll
        for (int nt = 0; nt < 8; nt++) {
            int col = wn * 64 + nt * 8 + t4 * 2;
            float bu0 = bus[col], bu1 = bus[col + 1];
            float bc0 = bcs[col], bc1 = bcs[col + 1];
            float2 o1, o2;
            o1.x = fmaxf(acc[mt][nt][0] + bu0 + m1 * bc0, 0.f);
            o1.y = fmaxf(acc[mt][nt][1] + bu1 + m1 * bc1, 0.f);
            o2.x = fmaxf(acc[mt][nt][2] + bu0 + m2 * bc0, 0.f);
            o2.y = fmaxf(acc[mt][nt][3] + bu1 + m2 * bc1, 0.f);
            if (row1 < N) {
                if (out32) *(float2*)(out32 + (size_t)row1 * DIM + col) = o1;
                if (out16) *(__half2*)(out16 + (size_t)row1 * DIM + col) = __floats2half2_rn(o1.x, o1.y);
            }
            if (row2 < N) {
                if (out32) *(float2*)(out32 + (size_t)row2 * DIM + col) = o2;
                if (out16) *(__half2*)(out16 + (size_t)row2 * DIM + col) = __floats2half2_rn(o2.x, o2.y);
            }
        }
    }
}

// ---------------- host orchestration ----------------
extern "C" void kernel_launch(void* const* d_in, const int* in_sizes, int n_in,
                              void* d_out, int out_size)
{
    const float* tile_h    = (const float*)d_in[0];
    const float* piece_h   = (const float*)d_in[1];
    const int*   tile_src  = (const int*)d_in[2];
    const int*   piece_dst = (const int*)d_in[3];
    const int*   piece_src = (const int*)d_in[4];
    const int*   tile_dst  = (const int*)d_in[5];
    const int*   t_src     = (const int*)d_in[6];
    const int*   t_dst     = (const int*)d_in[7];

    int NT  = in_sizes[0] / DIM;
    int NP  = in_sizes[1] / DIM;
    int EPT = in_sizes[2];
    int ETT = in_sizes[6];

    float* out       = (float*)d_out;
    float* out_tile  = out;
    float* out_piece = out + (size_t)NT * DIM;

    __half *th16_p, *ph16_p, *pout16_p, *tout16_p;
    int *cnt_p;
    cudaGetSymbolAddress((void**)&th16_p, g_th16);
    cudaGetSymbolAddress((void**)&ph16_p, g_ph16);
    cudaGetSymbolAddress((void**)&pout16_p, g_pout16);
    cudaGetSymbolAddress((void**)&tout16_p, g_tout16);
    cudaGetSymbolAddress((void**)&cnt_p, g_cnt);

    int convN = NT * 32 + NP * 32;
    convert_kernel<<<(convN + 255) / 256, 256>>>(tile_h, NT * 32, piece_h, NP * 32);

    prep_weights_kernel<<<dim3(128, 3), 128>>>(
        (const float*)d_in[8],  (const float*)d_in[9],  (const float*)d_in[10],
        (const float*)d_in[12], (const float*)d_in[13], (const float*)d_in[14],
        (const float*)d_in[16], (const float*)d_in[17], (const float*)d_in[18]);

    cudaMemsetAsync(cnt_p, 0, 3 * (size_t)MAXN * sizeof(int));
    int maxE = ETT > EPT ? ETT : EPT;
    dim3 cg((maxE + 255) / 256, 3);
    count3_kernel<<<cg, 256>>>(piece_dst, EPT, tile_dst, EPT, t_dst, ETT);

    int maxN = NT > NP ? NT : NP;
    dim3 sg((maxN + TILE - 1) / TILE, 3);
    tilesum_kernel<<<sg, 256>>>(NP, NT, NT);
    tileoff_kernel<<<1, 32>>>(NP, NT, NT);
    scanC_kernel<<<sg, 256>>>(NP, NT, NT);

    fill3_kernel<<<cg, 256>>>(tile_src, piece_dst, EPT,
                              piece_src, tile_dst, EPT,
                              t_src, t_dst, ETT);

    // Stage 1: tile -> piece
    agg_kernel<<<(NP + 7) / 8, 256>>>(0, th16_p, NP);
    update_mma_kernel<<<(NP + 127) / 128, 256>>>(
        0, ph16_p, (const float*)d_in[11], out_piece, pout16_p, NP);

    // Stage 2: piece -> tile
    agg_kernel<<<(NT + 7) / 8, 256>>>(1, pout16_p, NT);
    update_mma_kernel<<<(NT + 127) / 128, 256>>>(
        1, th16_p, (const float*)d_in[15], nullptr, tout16_p, NT);

    // Stage 3: tile -> tile
    agg_kernel<<<(NT + 7) / 8, 256>>>(2, tout16_p, NT);
    update_mma_kernel<<<(NT + 127) / 128, 256>>>(
        2, tout16_p, (const float*)d_in[19], out_tile, nullptr, NT);
}

// round 7
// speedup vs baseline: 3.4747x; 1.0652x over previous
#include <cuda_runtime.h>
#include <cuda_fp16.h>
#include <cstdint>
#include <math.h>

#define DIM 128
#define MAXN 50000
#define MAXP 25000
#define MAXE 600000
#define TILE 4096
#define MAXTILES 16

// ---------------- device scratch ----------------
__device__ __half g_th16[(size_t)MAXN * DIM];
__device__ __half g_ph16[(size_t)MAXP * DIM];
__device__ __half g_pout16[(size_t)MAXP * DIM];
__device__ __half g_tout16[(size_t)MAXN * DIM];
__device__ __half g_S16[(size_t)MAXN * DIM];
__device__ __half g_W216[3 * 128 * 256];
__device__ float  g_bc[3 * DIM];
__device__ int    g_cnt[3][MAXN];
__device__ int    g_rowptr[3][MAXN + 1];
__device__ int    g_cursor[3][MAXN];
__device__ int    g_srclist[3][MAXE];
__device__ int    g_tilesum[3][MAXTILES];

__device__ __forceinline__ void mma_f16(float* c, const uint32_t* a, uint32_t b0, uint32_t b1) {
    asm volatile(
        "mma.sync.aligned.m16n8k16.row.col.f32.f16.f16.f32 "
        "{%0,%1,%2,%3}, {%4,%5,%6,%7}, {%8,%9}, {%0,%1,%2,%3};"
        : "+f"(c[0]), "+f"(c[1]), "+f"(c[2]), "+f"(c[3])
        : "r"(a[0]), "r"(a[1]), "r"(a[2]), "r"(a[3]), "r"(b0), "r"(b1));
}

// ---------------- fused: convert (fp32->fp16) + count (3 stages) + weight prep ----------------
// Block ranges: [0,BC)=convert, [BC,BC+BE0+BE1+BE2)=count, rest = prep (2 j per block).
__global__ __launch_bounds__(256) void fused_front_kernel(
    const float* __restrict__ th, int ntv, const float* __restrict__ ph, int npv,
    const int* __restrict__ d0, int E0, const int* __restrict__ d1, int E1,
    const int* __restrict__ d2, int E2,
    int BC, int BE0, int BE1, int BE2,
    const float* __restrict__ W_t2p, const float* __restrict__ b_t2p, const float* __restrict__ W_pu,
    const float* __restrict__ W_p2t, const float* __restrict__ b_p2t, const float* __restrict__ W_tup,
    const float* __restrict__ W_t2t, const float* __restrict__ b_t2t, const float* __restrict__ W_tut)
{
    int b = blockIdx.x;
    int t = threadIdx.x;

    if (b < BC) {
        // convert: each thread converts 4 floats
        int i = b * 256 + t;
        int tot = ntv + npv;
        if (i >= tot) return;
        if (i < ntv) {
            float4 v = *(const float4*)(th + (size_t)i * 4);
            __half2* d = (__half2*)(g_th16 + (size_t)i * 4);
            d[0] = __floats2half2_rn(v.x, v.y);
            d[1] = __floats2half2_rn(v.z, v.w);
        } else {
            int j = i - ntv;
            float4 v = *(const float4*)(ph + (size_t)j * 4);
            __half2* d = (__half2*)(g_ph16 + (size_t)j * 4);
            d[0] = __floats2half2_rn(v.x, v.y);
            d[1] = __floats2half2_rn(v.z, v.w);
        }
        return;
    }
    b -= BC;
    if (b < BE0 + BE1 + BE2) {
        // count: 4 edges per thread via int4
        int s, bl;
        const int* dst;
        int E;
        if (b < BE0)            { s = 0; bl = b;             dst = d0; E = E0; }
        else if (b < BE0 + BE1) { s = 1; bl = b - BE0;       dst = d1; E = E1; }
        else                    { s = 2; bl = b - BE0 - BE1; dst = d2; E = E2; }
        int e = (bl * 256 + t) * 4;
        int* cnt = g_cnt[s];
        if (e + 3 < E) {
            int4 v = *(const int4*)(dst + e);
            atomicAdd(&cnt[v.x], 1);
            atomicAdd(&cnt[v.y], 1);
            atomicAdd(&cnt[v.z], 1);
            atomicAdd(&cnt[v.w], 1);
        } else {
            for (int q = 0; q < 4 && e + q < E; q++)
                atomicAdd(&cnt[dst[e + q]], 1);
        }
        return;
    }
    b -= BE0 + BE1 + BE2;
    // prep: 2 j-units per block; unit = s*128 + j
    {
        int unit = b * 2 + (t >> 7);
        if (unit >= 384) return;
        int s = unit >> 7;
        int j = unit & 127;
        int k = t & 127;

        const float *Wm, *Wu, *bm;
        if (s == 0)      { Wm = W_t2p; Wu = W_pu;  bm = b_t2p; }
        else if (s == 1) { Wm = W_p2t; Wu = W_tup; bm = b_p2t; }
        else             { Wm = W_t2t; Wu = W_tut; bm = b_t2t; }

        __half* W2s = g_W216 + (size_t)s * 128 * 256;
        W2s[j * 256 + k] = __float2half_rn(Wu[j * 256 + k]);

        float acc = 0.f;
        #pragma unroll 8
        for (int l = 0; l < 128; l++)
            acc = fmaf(Wu[j * 256 + 128 + l], Wm[l * DIM + k], acc);
        W2s[j * 256 + 128 + k] = __float2half_rn(acc);

        if (k == 0) {
            float a = 0.f;
            for (int l = 0; l < 128; l++)
                a = fmaf(Wu[j * 256 + 128 + l], bm[l], a);
            g_bc[s * DIM + j] = a;
        }
    }
}

// ---- scan phase A: per-tile sums ----
__global__ void tilesum_kernel(int N0, int N1, int N2)
{
    __shared__ int wsum[8];
    int s = blockIdx.y;
    int N = (s == 0) ? N0 : (s == 1) ? N1 : N2;
    int base = blockIdx.x * TILE;
    if (base >= N) return;
    const int* cnt = g_cnt[s];
    int t = threadIdx.x;
    int local = 0;
    #pragma unroll
    for (int q = 0; q < 4; q++) {
        int i = base + (t + q * 256) * 4;
        if (i + 3 < N) {
            int4 v = *(const int4*)(cnt + i);
            local += v.x + v.y + v.z + v.w;
        } else {
            for (int j = 0; j < 4; j++)
                if (i + j < N) local += cnt[i + j];
        }
    }
    #pragma unroll
    for (int off = 16; off > 0; off >>= 1)
        local += __shfl_down_sync(0xFFFFFFFF, local, off);
    if ((t & 31) == 0) wsum[t >> 5] = local;
    __syncthreads();
    if (t == 0) {
        int tot = 0;
        #pragma unroll
        for (int w = 0; w < 8; w++) tot += wsum[w];
        g_tilesum[s][blockIdx.x] = tot;
    }
}

// ---- scan phase B: per-tile block scan; each block derives its own tile offset ----
__global__ void scanC_kernel(int N0, int N1, int N2)
{
    __shared__ int wsum[8];
    __shared__ int wexcl[8];
    __shared__ int tile_off;
    int s = blockIdx.y;
    int N = (s == 0) ? N0 : (s == 1) ? N1 : N2;
    int base = blockIdx.x * TILE;
    if (base >= N) return;
    const int* cnt = g_cnt[s];
    int* rowptr = g_rowptr[s];
    int* cursor = g_cursor[s];
    int t = threadIdx.x;
    int lane = t & 31, wid = t >> 5;
    int ntiles = (N + TILE - 1) / TILE;

    if (t == 0) {
        int off = 0;
        for (int i = 0; i < (int)blockIdx.x; i++) off += g_tilesum[s][i];
        tile_off = off;
        if ((int)blockIdx.x == ntiles - 1)
            rowptr[N] = off + g_tilesum[s][blockIdx.x];
    }

    int e0 = base + t * 16;
    int c[16];
    #pragma unroll
    for (int q = 0; q < 16; q++) {
        int i = e0 + q;
        c[q] = (i < N) ? cnt[i] : 0;
    }
    int tot = 0;
    #pragma unroll
    for (int q = 0; q < 16; q++) tot += c[q];

    int x = tot;
    #pragma unroll
    for (int off = 1; off < 32; off <<= 1) {
        int y = __shfl_up_sync(0xFFFFFFFF, x, off);
        if (lane >= off) x += y;
    }
    int texcl = x - tot;
    if (lane == 31) wsum[wid] = x;
    __syncthreads();
    if (t == 0) {
        int run = 0;
        #pragma unroll
        for (int w = 0; w < 8; w++) { wexcl[w] = run; run += wsum[w]; }
    }
    __syncthreads();

    int pre = tile_off + wexcl[wid] + texcl;
    #pragma unroll
    for (int q = 0; q < 16; q++) {
        int i = e0 + q;
        if (i < N) { rowptr[i] = pre; cursor[i] = pre; }
        pre += c[q];
    }
}

// ---- fill: 4 edges per thread ----
__global__ void fill3_kernel(const int* __restrict__ s0, const int* __restrict__ d0, int E0,
                             const int* __restrict__ s1, const int* __restrict__ d1, int E1,
                             const int* __restrict__ s2, const int* __restrict__ d2, int E2)
{
    int s = blockIdx.y;
    const int* src = (s == 0) ? s0 : (s == 1) ? s1 : s2;
    const int* dst = (s == 0) ? d0 : (s == 1) ? d1 : d2;
    int E = (s == 0) ? E0 : (s == 1) ? E1 : E2;
    int e = (blockIdx.x * blockDim.x + threadIdx.x) * 4;
    int* cursor = g_cursor[s];
    int* srclist = g_srclist[s];
    if (e + 3 < E) {
        int4 d = *(const int4*)(dst + e);
        int4 sv = *(const int4*)(src + e);
        srclist[atomicAdd(&cursor[d.x], 1)] = sv.x;
        srclist[atomicAdd(&cursor[d.y], 1)] = sv.y;
        srclist[atomicAdd(&cursor[d.z], 1)] = sv.z;
        srclist[atomicAdd(&cursor[d.w], 1)] = sv.w;
    } else {
        for (int q = 0; q < 4 && e + q < E; q++) {
            int d = dst[e + q];
            srclist[atomicAdd(&cursor[d], 1)] = src[e + q];
        }
    }
}

// ---------------- aggregation: warp per row, 4-way index prefetch ----------------
__global__ void agg_kernel(int stage, const __half* __restrict__ H, int N)
{
    int w = (blockIdx.x * blockDim.x + threadIdx.x) >> 5;
    int lane = threadIdx.x & 31;
    if (w >= N) return;
    const int* rowptr = g_rowptr[stage];
    const int* srclist = g_srclist[stage];
    int s0 = rowptr[w];
    int s1 = rowptr[w + 1];
    float a0 = 0.f, a1 = 0.f, a2 = 0.f, a3 = 0.f;
    int i = s0;
    for (; i + 4 <= s1; i += 4) {
        int j0 = srclist[i], j1 = srclist[i + 1], j2 = srclist[i + 2], j3 = srclist[i + 3];
        uint2 v0 = *(const uint2*)(H + (size_t)j0 * DIM + lane * 4);
        uint2 v1 = *(const uint2*)(H + (size_t)j1 * DIM + lane * 4);
        uint2 v2 = *(const uint2*)(H + (size_t)j2 * DIM + lane * 4);
        uint2 v3 = *(const uint2*)(H + (size_t)j3 * DIM + lane * 4);
        float2 f;
        f = __half22float2(*(__half2*)&v0.x); a0 += f.x; a1 += f.y;
        f = __half22float2(*(__half2*)&v0.y); a2 += f.x; a3 += f.y;
        f = __half22float2(*(__half2*)&v1.x); a0 += f.x; a1 += f.y;
        f = __half22float2(*(__half2*)&v1.y); a2 += f.x; a3 += f.y;
        f = __half22float2(*(__half2*)&v2.x); a0 += f.x; a1 += f.y;
        f = __half22float2(*(__half2*)&v2.y); a2 += f.x; a3 += f.y;
        f = __half22float2(*(__half2*)&v3.x); a0 += f.x; a1 += f.y;
        f = __half22float2(*(__half2*)&v3.y); a2 += f.x; a3 += f.y;
    }
    for (; i < s1; i++) {
        int j = srclist[i];
        uint2 v = *(const uint2*)(H + (size_t)j * DIM + lane * 4);
        float2 f;
        f = __half22float2(*(__half2*)&v.x); a0 += f.x; a1 += f.y;
        f = __half22float2(*(__half2*)&v.y); a2 += f.x; a3 += f.y;
    }
    int cn = s1 - s0;
    float inv = (cn > 0) ? (1.f / (float)cn) : 0.f;
    uint2 o;
    *(__half2*)&o.x = __floats2half2_rn(a0 * inv, a1 * inv);
    *(__half2*)&o.y = __floats2half2_rn(a2 * inv, a3 * inv);
    *(uint2*)(g_S16 + (size_t)w * DIM + lane * 4) = o;
}

// ---------------- fp16 mma.sync update GEMM ----------------
#define XSTRH 72

__global__ __launch_bounds__(256) void update_mma_kernel(
    int stage, const __half* __restrict__ H,
    const float* __restrict__ bu,
    float* __restrict__ out32, __half* __restrict__ out16, int N)
{
    __shared__ __half As[128 * XSTRH];
    __shared__ __half Bs[128 * XSTRH];
    __shared__ float ms[128], bus[128], bcs[128];

    int t = threadIdx.x;
    int r0 = blockIdx.x * 128;
    const __half* W2 = g_W216 + (size_t)stage * 128 * 256;

    if (t < 128) {
        int row = r0 + t;
        int c = (row < N) ? g_cnt[stage][row] : 0;
        ms[t]  = (c > 0) ? 1.f : 0.f;
        bus[t] = bu[t];
        bcs[t] = g_bc[stage * DIM + t];
    }

    int lane = t & 31;
    int wid  = t >> 5;
    int g  = lane >> 2;
    int t4 = lane & 3;
    int wm = wid >> 1;
    int wn = wid & 1;

    float acc[2][8][4];
    #pragma unroll
    for (int mt = 0; mt < 2; mt++)
        #pragma unroll
        for (int nt = 0; nt < 8; nt++)
            #pragma unroll
            for (int i = 0; i < 4; i++) acc[mt][nt][i] = 0.f;

    for (int kc = 0; kc < 4; kc++) {
        __syncthreads();
        #pragma unroll
        for (int q = 0; q < 4; q++) {
            int id = t + 256 * q;
            int rl = id >> 3;
            int c8 = id & 7;
            int kg = kc * 64 + c8 * 8;
            int row = r0 + rl;
            uint4 v = make_uint4(0u, 0u, 0u, 0u);
            if (row < N) {
                const __half* src = (kg < 128)
                    ? (H + (size_t)row * DIM + kg)
                    : (g_S16 + (size_t)row * DIM + (kg - 128));
                v = *(const uint4*)src;
            }
            *(uint4*)&As[rl * XSTRH + c8 * 8] = v;
        }
        #pragma unroll
        for (int q = 0; q < 4; q++) {
            int id = t + 256 * q;
            int nl = id >> 3;
            int c8 = id & 7;
            uint4 v = *(const uint4*)(W2 + (size_t)nl * 256 + kc * 64 + c8 * 8);
            *(uint4*)&Bs[nl * XSTRH + c8 * 8] = v;
        }
        __syncthreads();

        #pragma unroll
        for (int ks = 0; ks < 4; ks++) {
            int kb = ks * 16;
            uint32_t a[2][4];
            #pragma unroll
            for (int mt = 0; mt < 2; mt++) {
                int rbase = (wm * 32 + mt * 16 + g) * XSTRH + kb + t4 * 2;
                a[mt][0] = *(const uint32_t*)&As[rbase];
                a[mt][1] = *(const uint32_t*)&As[rbase + 8 * XSTRH];
                a[mt][2] = *(const uint32_t*)&As[rbase + 8];
                a[mt][3] = *(const uint32_t*)&As[rbase + 8 * XSTRH + 8];
            }
            #pragma unroll
            for (int nt = 0; nt < 8; nt++) {
                int bbase = (wn * 64 + nt * 8 + g) * XSTRH + kb + t4 * 2;
                uint32_t b0 = *(const uint32_t*)&Bs[bbase];
                uint32_t b1 = *(const uint32_t*)&Bs[bbase + 8];
                mma_f16(acc[0][nt], a[0], b0, b1);
                mma_f16(acc[1][nt], a[1], b0, b1);
            }
        }
    }

    #pragma unroll
    for (int mt = 0; mt < 2; mt++) {
        int rl1 = wm * 32 + mt * 16 + g;
        int row1 = r0 + rl1;
        int row2 = row1 + 8;
        float m1 = ms[rl1], m2 = ms[rl1 + 8];
        #pragma unroll
        for (int nt = 0; nt < 8; nt++) {
            int col = wn * 64 + nt * 8 + t4 * 2;
            float bu0 = bus[col], bu1 = bus[col + 1];
            float bc0 = bcs[col], bc1 = bcs[col + 1];
            float2 o1, o2;
            o1.x = fmaxf(acc[mt][nt][0] + bu0 + m1 * bc0, 0.f);
            o1.y = fmaxf(acc[mt][nt][1] + bu1 + m1 * bc1, 0.f);
            o2.x = fmaxf(acc[mt][nt][2] + bu0 + m2 * bc0, 0.f);
            o2.y = fmaxf(acc[mt][nt][3] + bu1 + m2 * bc1, 0.f);
            if (row1 < N) {
                if (out32) *(float2*)(out32 + (size_t)row1 * DIM + col) = o1;
                if (out16) *(__half2*)(out16 + (size_t)row1 * DIM + col) = __floats2half2_rn(o1.x, o1.y);
            }
            if (row2 < N) {
                if (out32) *(float2*)(out32 + (size_t)row2 * DIM + col) = o2;
                if (out16) *(__half2*)(out16 + (size_t)row2 * DIM + col) = __floats2half2_rn(o2.x, o2.y);
            }
        }
    }
}

// ---------------- host orchestration ----------------
extern "C" void kernel_launch(void* const* d_in, const int* in_sizes, int n_in,
                              void* d_out, int out_size)
{
    const float* tile_h    = (const float*)d_in[0];
    const float* piece_h   = (const float*)d_in[1];
    const int*   tile_src  = (const int*)d_in[2];
    const int*   piece_dst = (const int*)d_in[3];
    const int*   piece_src = (const int*)d_in[4];
    const int*   tile_dst  = (const int*)d_in[5];
    const int*   t_src     = (const int*)d_in[6];
    const int*   t_dst     = (const int*)d_in[7];

    int NT  = in_sizes[0] / DIM;
    int NP  = in_sizes[1] / DIM;
    int EPT = in_sizes[2];
    int ETT = in_sizes[6];

    float* out       = (float*)d_out;
    float* out_tile  = out;
    float* out_piece = out + (size_t)NT * DIM;

    __half *th16_p, *ph16_p, *pout16_p, *tout16_p;
    int *cnt_p;
    cudaGetSymbolAddress((void**)&th16_p, g_th16);
    cudaGetSymbolAddress((void**)&ph16_p, g_ph16);
    cudaGetSymbolAddress((void**)&pout16_p, g_pout16);
    cudaGetSymbolAddress((void**)&tout16_p, g_tout16);
    cudaGetSymbolAddress((void**)&cnt_p, g_cnt);

    cudaMemsetAsync(cnt_p, 0, 3 * (size_t)MAXN * sizeof(int));

    // fused front: convert + count(3 stages) + weight prep
    int ntv = NT * 32, npv = NP * 32;
    int BC  = (ntv + npv + 255) / 256;
    int BE0 = (EPT + 1023) / 1024;
    int BE1 = (EPT + 1023) / 1024;
    int BE2 = (ETT + 1023) / 1024;
    int BP  = 192;
    fused_front_kernel<<<BC + BE0 + BE1 + BE2 + BP, 256>>>(
        tile_h, ntv, piece_h, npv,
        piece_dst, EPT, tile_dst, EPT, t_dst, ETT,
        BC, BE0, BE1, BE2,
        (const float*)d_in[8],  (const float*)d_in[9],  (const float*)d_in[10],
        (const float*)d_in[12], (const float*)d_in[13], (const float*)d_in[14],
        (const float*)d_in[16], (const float*)d_in[17], (const float*)d_in[18]);

    int maxN = NT > NP ? NT : NP;
    dim3 sg((maxN + TILE - 1) / TILE, 3);
    tilesum_kernel<<<sg, 256>>>(NP, NT, NT);
    scanC_kernel<<<sg, 256>>>(NP, NT, NT);

    int maxE = ETT > EPT ? ETT : EPT;
    dim3 fg((maxE + 1023) / 1024, 3);
    fill3_kernel<<<fg, 256>>>(tile_src, piece_dst, EPT,
                              piece_src, tile_dst, EPT,
                              t_src, t_dst, ETT);

    // Stage 1: tile -> piece
    agg_kernel<<<(NP + 7) / 8, 256>>>(0, th16_p, NP);
    update_mma_kernel<<<(NP + 127) / 128, 256>>>(
        0, ph16_p, (const float*)d_in[11], out_piece, pout16_p, NP);

    // Stage 2: piece -> tile
    agg_kernel<<<(NT + 7) / 8, 256>>>(1, pout16_p, NT);
    update_mma_kernel<<<(NT + 127) / 128, 256>>>(
        1, th16_p, (const float*)d_in[15], nullptr, tout16_p, NT);

    // Stage 3: tile -> tile
    agg_kernel<<<(NT + 7) / 8, 256>>>(2, tout16_p, NT);
    update_mma_kernel<<<(NT + 127) / 128, 256>>>(
        2, tout16_p, (const float*)d_in[19], out_tile, nullptr, NT);
}

// round 8
// speedup vs baseline: 3.5180x; 1.0125x over previous
#include <cuda_runtime.h>
#include <cuda_fp16.h>
#include <cstdint>
#include <math.h>

#define DIM 128
#define MAXN 50000
#define MAXP 25000
#define MAXE 600000
#define TILE 4096
#define MAXTILES 16

// ---------------- device scratch ----------------
__device__ __half g_th16[(size_t)MAXN * DIM];
__device__ __half g_ph16[(size_t)MAXP * DIM];
__device__ __half g_pout16[(size_t)MAXP * DIM];
__device__ __half g_tout16[(size_t)MAXN * DIM];
__device__ __half g_S16[(size_t)MAXN * DIM];
__device__ __half g_W216[3 * 128 * 256];
__device__ float  g_bc[3 * DIM];
__device__ int    g_cnt[3][MAXN];
__device__ int    g_rowptr[3][MAXN + 1];
__device__ int    g_rank[3][MAXE];
__device__ int    g_srclist[3][MAXE];
__device__ int    g_tilesum[3][MAXTILES];

__device__ __forceinline__ void mma_f16(float* c, const uint32_t* a, uint32_t b0, uint32_t b1) {
    asm volatile(
        "mma.sync.aligned.m16n8k16.row.col.f32.f16.f16.f32 "
        "{%0,%1,%2,%3}, {%4,%5,%6,%7}, {%8,%9}, {%0,%1,%2,%3};"
        : "+f"(c[0]), "+f"(c[1]), "+f"(c[2]), "+f"(c[3])
        : "r"(a[0]), "r"(a[1]), "r"(a[2]), "r"(a[3]), "r"(b0), "r"(b1));
}

// ---------------- fused: convert + count(+rank) + weight prep ----------------
__global__ __launch_bounds__(256) void fused_front_kernel(
    const float* __restrict__ th, int ntv, const float* __restrict__ ph, int npv,
    const int* __restrict__ d0, int E0, const int* __restrict__ d1, int E1,
    const int* __restrict__ d2, int E2,
    int BC, int BE0, int BE1, int BE2,
    const float* __restrict__ W_t2p, const float* __restrict__ b_t2p, const float* __restrict__ W_pu,
    const float* __restrict__ W_p2t, const float* __restrict__ b_p2t, const float* __restrict__ W_tup,
    const float* __restrict__ W_t2t, const float* __restrict__ b_t2t, const float* __restrict__ W_tut)
{
    int b = blockIdx.x;
    int t = threadIdx.x;

    if (b < BC) {
        int i = b * 256 + t;
        int tot = ntv + npv;
        if (i >= tot) return;
        if (i < ntv) {
            float4 v = *(const float4*)(th + (size_t)i * 4);
            __half2* d = (__half2*)(g_th16 + (size_t)i * 4);
            d[0] = __floats2half2_rn(v.x, v.y);
            d[1] = __floats2half2_rn(v.z, v.w);
        } else {
            int j = i - ntv;
            float4 v = *(const float4*)(ph + (size_t)j * 4);
            __half2* d = (__half2*)(g_ph16 + (size_t)j * 4);
            d[0] = __floats2half2_rn(v.x, v.y);
            d[1] = __floats2half2_rn(v.z, v.w);
        }
        return;
    }
    b -= BC;
    if (b < BE0 + BE1 + BE2) {
        // count + rank capture: 4 edges per thread
        int s, bl;
        const int* dst;
        int E;
        if (b < BE0)            { s = 0; bl = b;             dst = d0; E = E0; }
        else if (b < BE0 + BE1) { s = 1; bl = b - BE0;       dst = d1; E = E1; }
        else                    { s = 2; bl = b - BE0 - BE1; dst = d2; E = E2; }
        int e = (bl * 256 + t) * 4;
        int* cnt = g_cnt[s];
        int* rank = g_rank[s];
        if (e + 3 < E) {
            int4 v = *(const int4*)(dst + e);
            int4 r;
            r.x = atomicAdd(&cnt[v.x], 1);
            r.y = atomicAdd(&cnt[v.y], 1);
            r.z = atomicAdd(&cnt[v.z], 1);
            r.w = atomicAdd(&cnt[v.w], 1);
            *(int4*)(rank + e) = r;
        } else {
            for (int q = 0; q < 4 && e + q < E; q++)
                rank[e + q] = atomicAdd(&cnt[dst[e + q]], 1);
        }
        return;
    }
    b -= BE0 + BE1 + BE2;
    {
        int unit = b * 2 + (t >> 7);
        if (unit >= 384) return;
        int s = unit >> 7;
        int j = unit & 127;
        int k = t & 127;

        const float *Wm, *Wu, *bm;
        if (s == 0)      { Wm = W_t2p; Wu = W_pu;  bm = b_t2p; }
        else if (s == 1) { Wm = W_p2t; Wu = W_tup; bm = b_p2t; }
        else             { Wm = W_t2t; Wu = W_tut; bm = b_t2t; }

        __half* W2s = g_W216 + (size_t)s * 128 * 256;
        W2s[j * 256 + k] = __float2half_rn(Wu[j * 256 + k]);

        float acc = 0.f;
        #pragma unroll 8
        for (int l = 0; l < 128; l++)
            acc = fmaf(Wu[j * 256 + 128 + l], Wm[l * DIM + k], acc);
        W2s[j * 256 + 128 + k] = __float2half_rn(acc);

        if (k == 0) {
            float a = 0.f;
            for (int l = 0; l < 128; l++)
                a = fmaf(Wu[j * 256 + 128 + l], bm[l], a);
            g_bc[s * DIM + j] = a;
        }
    }
}

// ---- scan phase A: per-tile sums ----
__global__ void tilesum_kernel(int N0, int N1, int N2)
{
    __shared__ int wsum[8];
    int s = blockIdx.y;
    int N = (s == 0) ? N0 : (s == 1) ? N1 : N2;
    int base = blockIdx.x * TILE;
    if (base >= N) return;
    const int* cnt = g_cnt[s];
    int t = threadIdx.x;
    int local = 0;
    #pragma unroll
    for (int q = 0; q < 4; q++) {
        int i = base + (t + q * 256) * 4;
        if (i + 3 < N) {
            int4 v = *(const int4*)(cnt + i);
            local += v.x + v.y + v.z + v.w;
        } else {
            for (int j = 0; j < 4; j++)
                if (i + j < N) local += cnt[i + j];
        }
    }
    #pragma unroll
    for (int off = 16; off > 0; off >>= 1)
        local += __shfl_down_sync(0xFFFFFFFF, local, off);
    if ((t & 31) == 0) wsum[t >> 5] = local;
    __syncthreads();
    if (t == 0) {
        int tot = 0;
        #pragma unroll
        for (int w = 0; w < 8; w++) tot += wsum[w];
        g_tilesum[s][blockIdx.x] = tot;
    }
}

// ---- scan phase B: per-tile block scan ----
__global__ void scanC_kernel(int N0, int N1, int N2)
{
    __shared__ int wsum[8];
    __shared__ int wexcl[8];
    __shared__ int tile_off;
    int s = blockIdx.y;
    int N = (s == 0) ? N0 : (s == 1) ? N1 : N2;
    int base = blockIdx.x * TILE;
    if (base >= N) return;
    const int* cnt = g_cnt[s];
    int* rowptr = g_rowptr[s];
    int t = threadIdx.x;
    int lane = t & 31, wid = t >> 5;
    int ntiles = (N + TILE - 1) / TILE;

    if (t == 0) {
        int off = 0;
        for (int i = 0; i < (int)blockIdx.x; i++) off += g_tilesum[s][i];
        tile_off = off;
        if ((int)blockIdx.x == ntiles - 1)
            rowptr[N] = off + g_tilesum[s][blockIdx.x];
    }

    int e0 = base + t * 16;
    int c[16];
    #pragma unroll
    for (int q = 0; q < 16; q++) {
        int i = e0 + q;
        c[q] = (i < N) ? cnt[i] : 0;
    }
    int tot = 0;
    #pragma unroll
    for (int q = 0; q < 16; q++) tot += c[q];

    int x = tot;
    #pragma unroll
    for (int off = 1; off < 32; off <<= 1) {
        int y = __shfl_up_sync(0xFFFFFFFF, x, off);
        if (lane >= off) x += y;
    }
    int texcl = x - tot;
    if (lane == 31) wsum[wid] = x;
    __syncthreads();
    if (t == 0) {
        int run = 0;
        #pragma unroll
        for (int w = 0; w < 8; w++) { wexcl[w] = run; run += wsum[w]; }
    }
    __syncthreads();

    int pre = tile_off + wexcl[wid] + texcl;
    #pragma unroll
    for (int q = 0; q < 16; q++) {
        int i = e0 + q;
        if (i < N) rowptr[i] = pre;
        pre += c[q];
    }
}

// ---- fill: atomic-free, pos = rowptr[dst] + rank ----
__global__ void fill3_kernel(const int* __restrict__ s0, const int* __restrict__ d0, int E0,
                             const int* __restrict__ s1, const int* __restrict__ d1, int E1,
                             const int* __restrict__ s2, const int* __restrict__ d2, int E2)
{
    int s = blockIdx.y;
    const int* src = (s == 0) ? s0 : (s == 1) ? s1 : s2;
    const int* dst = (s == 0) ? d0 : (s == 1) ? d1 : d2;
    int E = (s == 0) ? E0 : (s == 1) ? E1 : E2;
    int e = (blockIdx.x * blockDim.x + threadIdx.x) * 4;
    const int* rowptr = g_rowptr[s];
    const int* rank = g_rank[s];
    int* srclist = g_srclist[s];
    if (e + 3 < E) {
        int4 d = *(const int4*)(dst + e);
        int4 sv = *(const int4*)(src + e);
        int4 r = *(const int4*)(rank + e);
        srclist[rowptr[d.x] + r.x] = sv.x;
        srclist[rowptr[d.y] + r.y] = sv.y;
        srclist[rowptr[d.z] + r.z] = sv.z;
        srclist[rowptr[d.w] + r.w] = sv.w;
    } else {
        for (int q = 0; q < 4 && e + q < E; q++)
            srclist[rowptr[dst[e + q]] + rank[e + q]] = src[e + q];
    }
}

// ---------------- aggregation: warp per row, 4-way index prefetch ----------------
__global__ void agg_kernel(int stage, const __half* __restrict__ H, int N)
{
    int w = (blockIdx.x * blockDim.x + threadIdx.x) >> 5;
    int lane = threadIdx.x & 31;
    if (w >= N) return;
    const int* rowptr = g_rowptr[stage];
    const int* srclist = g_srclist[stage];
    int s0 = rowptr[w];
    int s1 = rowptr[w + 1];
    float a0 = 0.f, a1 = 0.f, a2 = 0.f, a3 = 0.f;
    int i = s0;
    for (; i + 4 <= s1; i += 4) {
        int j0 = srclist[i], j1 = srclist[i + 1], j2 = srclist[i + 2], j3 = srclist[i + 3];
        uint2 v0 = *(const uint2*)(H + (size_t)j0 * DIM + lane * 4);
        uint2 v1 = *(const uint2*)(H + (size_t)j1 * DIM + lane * 4);
        uint2 v2 = *(const uint2*)(H + (size_t)j2 * DIM + lane * 4);
        uint2 v3 = *(const uint2*)(H + (size_t)j3 * DIM + lane * 4);
        float2 f;
        f = __half22float2(*(__half2*)&v0.x); a0 += f.x; a1 += f.y;
        f = __half22float2(*(__half2*)&v0.y); a2 += f.x; a3 += f.y;
        f = __half22float2(*(__half2*)&v1.x); a0 += f.x; a1 += f.y;
        f = __half22float2(*(__half2*)&v1.y); a2 += f.x; a3 += f.y;
        f = __half22float2(*(__half2*)&v2.x); a0 += f.x; a1 += f.y;
        f = __half22float2(*(__half2*)&v2.y); a2 += f.x; a3 += f.y;
        f = __half22float2(*(__half2*)&v3.x); a0 += f.x; a1 += f.y;
        f = __half22float2(*(__half2*)&v3.y); a2 += f.x; a3 += f.y;
    }
    for (; i < s1; i++) {
        int j = srclist[i];
        uint2 v = *(const uint2*)(H + (size_t)j * DIM + lane * 4);
        float2 f;
        f = __half22float2(*(__half2*)&v.x); a0 += f.x; a1 += f.y;
        f = __half22float2(*(__half2*)&v.y); a2 += f.x; a3 += f.y;
    }
    int cn = s1 - s0;
    float inv = (cn > 0) ? (1.f / (float)cn) : 0.f;
    uint2 o;
    *(__half2*)&o.x = __floats2half2_rn(a0 * inv, a1 * inv);
    *(__half2*)&o.y = __floats2half2_rn(a2 * inv, a3 * inv);
    *(uint2*)(g_S16 + (size_t)w * DIM + lane * 4) = o;
}

// ---------------- fp16 mma.sync update GEMM ----------------
#define XSTRH 72

__global__ __launch_bounds__(256) void update_mma_kernel(
    int stage, const __half* __restrict__ H,
    const float* __restrict__ bu,
    float* __restrict__ out32, __half* __restrict__ out16, int N)
{
    __shared__ __half As[128 * XSTRH];
    __shared__ __half Bs[128 * XSTRH];
    __shared__ float ms[128], bus[128], bcs[128];

    int t = threadIdx.x;
    int r0 = blockIdx.x * 128;
    const __half* W2 = g_W216 + (size_t)stage * 128 * 256;

    if (t < 128) {
        int row = r0 + t;
        int c = (row < N) ? g_cnt[stage][row] : 0;
        ms[t]  = (c > 0) ? 1.f : 0.f;
        bus[t] = bu[t];
        bcs[t] = g_bc[stage * DIM + t];
    }

    int lane = t & 31;
    int wid  = t >> 5;
    int g  = lane >> 2;
    int t4 = lane & 3;
    int wm = wid >> 1;
    int wn = wid & 1;

    float acc[2][8][4];
    #pragma unroll
    for (int mt = 0; mt < 2; mt++)
        #pragma unroll
        for (int nt = 0; nt < 8; nt++)
            #pragma unroll
            for (int i = 0; i < 4; i++) acc[mt][nt][i] = 0.f;

    for (int kc = 0; kc < 4; kc++) {
        __syncthreads();
        #pragma unroll
        for (int q = 0; q < 4; q++) {
            int id = t + 256 * q;
            int rl = id >> 3;
            int c8 = id & 7;
            int kg = kc * 64 + c8 * 8;
            int row = r0 + rl;
            uint4 v = make_uint4(0u, 0u, 0u, 0u);
            if (row < N) {
                const __half* src = (kg < 128)
                    ? (H + (size_t)row * DIM + kg)
                    : (g_S16 + (size_t)row * DIM + (kg - 128));
                v = *(const uint4*)src;
            }
            *(uint4*)&As[rl * XSTRH + c8 * 8] = v;
        }
        #pragma unroll
        for (int q = 0; q < 4; q++) {
            int id = t + 256 * q;
            int nl = id >> 3;
            int c8 = id & 7;
            uint4 v = *(const uint4*)(W2 + (size_t)nl * 256 + kc * 64 + c8 * 8);
            *(uint4*)&Bs[nl * XSTRH + c8 * 8] = v;
        }
        __syncthreads();

        #pragma unroll
        for (int ks = 0; ks < 4; ks++) {
            int kb = ks * 16;
            uint32_t a[2][4];
            #pragma unroll
            for (int mt = 0; mt < 2; mt++) {
                int rbase = (wm * 32 + mt * 16 + g) * XSTRH + kb + t4 * 2;
                a[mt][0] = *(const uint32_t*)&As[rbase];
                a[mt][1] = *(const uint32_t*)&As[rbase + 8 * XSTRH];
                a[mt][2] = *(const uint32_t*)&As[rbase + 8];
                a[mt][3] = *(const uint32_t*)&As[rbase + 8 * XSTRH + 8];
            }
            #pragma unroll
            for (int nt = 0; nt < 8; nt++) {
                int bbase = (wn * 64 + nt * 8 + g) * XSTRH + kb + t4 * 2;
                uint32_t b0 = *(const uint32_t*)&Bs[bbase];
                uint32_t b1 = *(const uint32_t*)&Bs[bbase + 8];
                mma_f16(acc[0][nt], a[0], b0, b1);
                mma_f16(acc[1][nt], a[1], b0, b1);
            }
        }
    }

    #pragma unroll
    for (int mt = 0; mt < 2; mt++) {
        int rl1 = wm * 32 + mt * 16 + g;
        int row1 = r0 + rl1;
        int row2 = row1 + 8;
        float m1 = ms[rl1], m2 = ms[rl1 + 8];
        #pragma unroll
        for (int nt = 0; nt < 8; nt++) {
            int col = wn * 64 + nt * 8 + t4 * 2;
            float bu0 = bus[col], bu1 = bus[col + 1];
            float bc0 = bcs[col], bc1 = bcs[col + 1];
            float2 o1, o2;
            o1.x = fmaxf(acc[mt][nt][0] + bu0 + m1 * bc0, 0.f);
            o1.y = fmaxf(acc[mt][nt][1] + bu1 + m1 * bc1, 0.f);
            o2.x = fmaxf(acc[mt][nt][2] + bu0 + m2 * bc0, 0.f);
            o2.y = fmaxf(acc[mt][nt][3] + bu1 + m2 * bc1, 0.f);
            if (row1 < N) {
                if (out32) *(float2*)(out32 + (size_t)row1 * DIM + col) = o1;
                if (out16) *(__half2*)(out16 + (size_t)row1 * DIM + col) = __floats2half2_rn(o1.x, o1.y);
            }
            if (row2 < N) {
                if (out32) *(float2*)(out32 + (size_t)row2 * DIM + col) = o2;
                if (out16) *(__half2*)(out16 + (size_t)row2 * DIM + col) = __floats2half2_rn(o2.x, o2.y);
            }
        }
    }
}

// ---------------- host orchestration ----------------
extern "C" void kernel_launch(void* const* d_in, const int* in_sizes, int n_in,
                              void* d_out, int out_size)
{
    const float* tile_h    = (const float*)d_in[0];
    const float* piece_h   = (const float*)d_in[1];
    const int*   tile_src  = (const int*)d_in[2];
    const int*   piece_dst = (const int*)d_in[3];
    const int*   piece_src = (const int*)d_in[4];
    const int*   tile_dst  = (const int*)d_in[5];
    const int*   t_src     = (const int*)d_in[6];
    const int*   t_dst     = (const int*)d_in[7];

    int NT  = in_sizes[0] / DIM;
    int NP  = in_sizes[1] / DIM;
    int EPT = in_sizes[2];
    int ETT = in_sizes[6];

    float* out       = (float*)d_out;
    float* out_tile  = out;
    float* out_piece = out + (size_t)NT * DIM;

    __half *th16_p, *ph16_p, *pout16_p, *tout16_p;
    int *cnt_p;
    cudaGetSymbolAddress((void**)&th16_p, g_th16);
    cudaGetSymbolAddress((void**)&ph16_p, g_ph16);
    cudaGetSymbolAddress((void**)&pout16_p, g_pout16);
    cudaGetSymbolAddress((void**)&tout16_p, g_tout16);
    cudaGetSymbolAddress((void**)&cnt_p, g_cnt);

    cudaMemsetAsync(cnt_p, 0, 3 * (size_t)MAXN * sizeof(int));

    int ntv = NT * 32, npv = NP * 32;
    int BC  = (ntv + npv + 255) / 256;
    int BE0 = (EPT + 1023) / 1024;
    int BE1 = (EPT + 1023) / 1024;
    int BE2 = (ETT + 1023) / 1024;
    int BP  = 192;
    fused_front_kernel<<<BC + BE0 + BE1 + BE2 + BP, 256>>>(
        tile_h, ntv, piece_h, npv,
        piece_dst, EPT, tile_dst, EPT, t_dst, ETT,
        BC, BE0, BE1, BE2,
        (const float*)d_in[8],  (const float*)d_in[9],  (const float*)d_in[10],
        (const float*)d_in[12], (const float*)d_in[13], (const float*)d_in[14],
        (const float*)d_in[16], (const float*)d_in[17], (const float*)d_in[18]);

    int maxN = NT > NP ? NT : NP;
    dim3 sg((maxN + TILE - 1) / TILE, 3);
    tilesum_kernel<<<sg, 256>>>(NP, NT, NT);
    scanC_kernel<<<sg, 256>>>(NP, NT, NT);

    int maxE = ETT > EPT ? ETT : EPT;
    dim3 fg((maxE + 1023) / 1024, 3);
    fill3_kernel<<<fg, 256>>>(tile_src, piece_dst, EPT,
                              piece_src, tile_dst, EPT,
                              t_src, t_dst, ETT);

    // Stage 1: tile -> piece
    agg_kernel<<<(NP + 7) / 8, 256>>>(0, th16_p, NP);
    update_mma_kernel<<<(NP + 127) / 128, 256>>>(
        0, ph16_p, (const float*)d_in[11], out_piece, pout16_p, NP);

    // Stage 2: piece -> tile
    agg_kernel<<<(NT + 7) / 8, 256>>>(1, pout16_p, NT);
    update_mma_kernel<<<(NT + 127) / 128, 256>>>(
        1, th16_p, (const float*)d_in[15], nullptr, tout16_p, NT);

    // Stage 3: tile -> tile
    agg_kernel<<<(NT + 7) / 8, 256>>>(2, tout16_p, NT);
    update_mma_kernel<<<(NT + 127) / 128, 256>>>(
        2, tout16_p, (const float*)d_in[19], out_tile, nullptr, NT);
}